// round 13
// baseline (speedup 1.0000x reference)
#include <cuda_runtime.h>
#include <cuda_bf16.h>
#include <cstdint>
#include <math.h>

#define EPSBN 1e-5f

#define NB 8
#define CIN 3
#define HIMG 256
#define WIMG 256
#define DD 64
#define KC 1024
#define HP 128
#define WP 128
#define NPTS (NB*HP*WP)            /* 131072 */
#define YELEMS (NB*CIN*HIMG*WIMG)  /* 1572864 */
#define BNCNT (NB*HIMG*WIMG)       /* 524288 per channel */

// ---------------- scratch (device globals; allocation-free) ----------------
__device__ float g_praw[NPTS*DD];
__device__ __align__(16) __nv_bfloat16 g_ehi[KC*DD];
__device__ __align__(16) __nv_bfloat16 g_elo[KC*DD];
__device__ int   g_idx[NPTS];
__device__ float g_y2[YELEMS];
__device__ __align__(16) float g_e2[KC];
__device__ float g_cw[48*64];
__device__ float g_part1[64*512*2];
__device__ float g_part2[3*256*2];
__device__ float g_bn1[64*2];
__device__ float g_bn2[3*2];
__device__ float g_losspart[2048];

// ---------------- mma / async helpers ----------------
#define LDSM_X4(r0,r1,r2,r3,addr) \
    asm volatile("ldmatrix.sync.aligned.m8n8.x4.shared.b16 {%0,%1,%2,%3},[%4];" \
        : "=r"(r0),"=r"(r1),"=r"(r2),"=r"(r3) : "r"(addr))
#define MMA16816(c,a0,a1,a2,a3,b0,b1) \
    asm volatile("mma.sync.aligned.m16n8k16.row.col.f32.bf16.bf16.f32 " \
        "{%0,%1,%2,%3},{%4,%5,%6,%7},{%8,%9},{%0,%1,%2,%3};" \
        : "+f"((c)[0]),"+f"((c)[1]),"+f"((c)[2]),"+f"((c)[3]) \
        : "r"(a0),"r"(a1),"r"(a2),"r"(a3),"r"(b0),"r"(b1))
#define CP_ASYNC16(dst, src) \
    asm volatile("cp.async.ca.shared.global [%0], [%1], 16;" \
        :: "r"(dst), "l"(src) : "memory")
#define CP_COMMIT() asm volatile("cp.async.commit_group;" ::: "memory")
#define CP_WAIT0()  asm volatile("cp.async.wait_group 0;" ::: "memory")

__device__ __forceinline__ bool better(float da, int ia, float db, int ib) {
    return da < db || (da == db && ia < ib);
}

// ============================================================
// conv1 + bias + fused BN1 stats + fused maxpool2
// grid (8,8,4): each block does batches z and z+4 (one full wave)
// ============================================================
__global__ void __launch_bounds__(256,2) conv1pool_k(const float* __restrict__ x,
                                                     const float* __restrict__ w,
                                                     const float* __restrict__ bias)
{
    __shared__ float s_in[3][34][34];
    __shared__ float s_w[64*27];
    __shared__ float s_b[64];
    __shared__ float s_sum[64*8];
    __shared__ float s_sq[64*8];
    extern __shared__ float s_pool[];   // [16][16][65]

    int tx = threadIdx.x, ty = threadIdx.y;
    int tid = ty*32 + tx;
    int wid = tid >> 5;
    int lane = tid & 31;
    int x0 = blockIdx.x*32, y0 = blockIdx.y*32;

    for (int i = tid; i < 64*27; i += 256) s_w[i] = w[i];
    if (tid < 64) s_b[tid] = bias[tid];

    const unsigned FULL = 0xffffffffu;
    int pxl = tx >> 1;
    int pr0 = ty*2;

    for (int bi = 0; bi < 2; bi++) {
        int b = blockIdx.z + bi*4;
        int bid = (b*8 + blockIdx.y)*8 + blockIdx.x;
        __syncthreads();
        for (int i = tid; i < 3*34*34; i += 256) {
            int c = i / (34*34); int r = i % (34*34);
            int yy = r / 34, xx = r % 34;
            int gy = y0 + yy - 1, gx = x0 + xx - 1;
            float v = 0.f;
            if (gy >= 0 && gy < 256 && gx >= 0 && gx < 256)
                v = x[((b*3 + c)*256 + gy)*256 + gx];
            s_in[c][yy][xx] = v;
        }
        __syncthreads();

        float rin[3][6][3];
#pragma unroll
        for (int c = 0; c < 3; c++)
#pragma unroll
            for (int r = 0; r < 6; r++)
#pragma unroll
                for (int q = 0; q < 3; q++)
                    rin[c][r][q] = s_in[c][ty*4 + r][tx + q];

        for (int co = 0; co < 64; co++) {
            float bb = s_b[co];
            float a0 = bb, a1 = bb, a2 = bb, a3 = bb;
#pragma unroll
            for (int c = 0; c < 3; c++)
#pragma unroll
                for (int ky = 0; ky < 3; ky++)
#pragma unroll
                    for (int kx = 0; kx < 3; kx++) {
                        float wv = s_w[co*27 + c*9 + ky*3 + kx];
                        a0 = fmaf(rin[c][0+ky][kx], wv, a0);
                        a1 = fmaf(rin[c][1+ky][kx], wv, a1);
                        a2 = fmaf(rin[c][2+ky][kx], wv, a2);
                        a3 = fmaf(rin[c][3+ky][kx], wv, a3);
                    }
            float s = a0 + a1 + a2 + a3;
            float q = a0*a0; q = fmaf(a1,a1,q); q = fmaf(a2,a2,q); q = fmaf(a3,a3,q);
#pragma unroll
            for (int o = 16; o > 0; o >>= 1) {
                s += __shfl_xor_sync(FULL, s, o);
                q += __shfl_xor_sync(FULL, q, o);
            }
            if (lane == 0) { s_sum[co*8 + wid] = s; s_sq[co*8 + wid] = q; }
            float m0 = fmaxf(a0, a1);
            float m1 = fmaxf(a2, a3);
            m0 = fmaxf(m0, __shfl_xor_sync(FULL, m0, 1));
            m1 = fmaxf(m1, __shfl_xor_sync(FULL, m1, 1));
            if ((tx & 1) == 0) {
                s_pool[(pr0*16 + pxl)*65 + co]     = m0;
                s_pool[((pr0+1)*16 + pxl)*65 + co] = m1;
            }
        }
        __syncthreads();

        if (tid < 64) {
            float S = 0.f, Q = 0.f;
#pragma unroll
            for (int i = 0; i < 8; i++) { S += s_sum[tid*8 + i]; Q += s_sq[tid*8 + i]; }
            g_part1[(tid*512 + bid)*2]     = S;
            g_part1[(tid*512 + bid)*2 + 1] = Q;
        }

        int base = (((b*128 + (y0 >> 1))*128) + (x0 >> 1))*64;
        for (int i = tid; i < 16384; i += 256) {
            int r = i >> 10, j = i & 1023;
            int px = j >> 6, co = j & 63;
            g_praw[base + r*8192 + j] = s_pool[(r*16 + px)*65 + co];
        }
    }
}

// ============================================================
// finalize BN1 (one block per channel)
// ============================================================
__global__ void __launch_bounds__(256) finalize1_k(const float* __restrict__ gamma,
                                                   const float* __restrict__ beta)
{
    int c = blockIdx.x, t = threadIdx.x;
    float s = 0.f, q = 0.f;
    for (int i = t; i < 512; i += 256) {
        s += g_part1[(c*512 + i)*2];
        q += g_part1[(c*512 + i)*2 + 1];
    }
    __shared__ float ss[256], s2[256];
    ss[t] = s; s2[t] = q; __syncthreads();
    for (int o = 128; o > 0; o >>= 1) {
        if (t < o) { ss[t] += ss[t+o]; s2[t] += s2[t+o]; }
        __syncthreads();
    }
    if (t == 0) {
        float inv = 1.f / (float)BNCNT;
        float mean = ss[0] * inv;
        float var = s2[0] * inv - mean*mean;
        float scale = gamma[c] * rsqrtf(var + EPSBN);
        g_bn1[c*2]   = scale;
        g_bn1[c*2+1] = beta[c] - mean*scale;
    }
}

// ============================================================
// prep2: embed bf16 split + ||e||^2 (blocks 0-127), conv2 weight
// collapse (blocks 128-139)
// ============================================================
__global__ void __launch_bounds__(256) prep2_k(const float* __restrict__ embed,
                                               const float* __restrict__ w2)
{
    int bb = blockIdx.x;
    int t = threadIdx.x;
    if (bb < 128) {
        int code = bb*8 + (t >> 5);
        int lane = t & 31;
        float a = embed[code*64 + lane];
        float b2v = embed[code*64 + 32 + lane];
        __nv_bfloat16 ah = __float2bfloat16(a);
        __nv_bfloat16 bh = __float2bfloat16(b2v);
        g_ehi[code*64 + lane] = ah;
        g_ehi[code*64 + 32 + lane] = bh;
        g_elo[code*64 + lane] = __float2bfloat16(a - __bfloat162float(ah));
        g_elo[code*64 + 32 + lane] = __float2bfloat16(b2v - __bfloat162float(bh));
        float s = a*a + b2v*b2v;
#pragma unroll
        for (int o = 16; o > 0; o >>= 1)
            s += __shfl_down_sync(0xffffffffu, s, o);
        if (lane == 0) g_e2[code] = s;
    } else {
        int e = (bb - 128)*256 + t;
        if (e < 48*64) {
            int d = e & 63;
            int rest = e >> 6;
            int tap = rest & 3;
            int tx_ = tap & 1, ty_ = tap >> 1;
            int co = (rest >> 2) % 3;
            int ph = rest / 12;
            int px = ph & 1, py = ph >> 1;
            float s = 0.f;
            for (int ky = 0; ky < 3; ky++) {
                int mapy = (py == 0) ? ((ky == 0) ? 0 : 1) : ((ky < 2) ? 0 : 1);
                if (mapy != ty_) continue;
                for (int kx = 0; kx < 3; kx++) {
                    int mapx = (px == 0) ? ((kx == 0) ? 0 : 1) : ((kx < 2) ? 0 : 1);
                    if (mapx != tx_) continue;
                    s += w2[((co*64 + d)*3 + ky)*3 + kx];
                }
            }
            g_cw[e] = s;
        }
    }
}

// ============================================================
// VQ: fused BN+ReLU+bf16-split of A (from g_praw) + hi/lo 3-GEMM
// via mma.sync with cp.async double-buffered B (1 sync/chunk).
// Packed-key top-2 + exact fp32 refine. Writes indices only.
// ============================================================
#define VQ_AHI  0
#define VQ_ALO  8192
#define VQ_POOL 16384
#define VQ_B0H  33792
#define VQ_B0L  41984
#define VQ_B1H  50176
#define VQ_B1L  58368
#define VQ_E2   66560
#define VQ_SMEM_SZ 70656

__global__ void __launch_bounds__(256,2) vq_k(const float* __restrict__ embed,
                                              float* __restrict__ out)
{
    extern __shared__ __align__(16) char vsmem[];
    __shared__ float s_ss[128];
    int t = threadIdx.x;
    int w = t >> 5, lane = t & 31;
    int rt = w & 1;
    int cq = w >> 1;
    int row0 = blockIdx.x * 64;
    unsigned int uBase = (unsigned int)__cvta_generic_to_shared(vsmem);
    const char* ehp = (const char*)g_ehi;
    const char* elp = (const char*)g_elo;

    if (t < 128) s_ss[t] = g_bn1[t];

    {
        unsigned int bh = uBase + VQ_B0H;
        unsigned int bl = uBase + VQ_B0L;
#pragma unroll
        for (int j = 0; j < 4; j++) {
            int idx = t + j*256;
            int e = idx & 511;
            int r = e >> 3, kc = e & 7;
            unsigned int doff = (unsigned int)((r*8 + (kc ^ (r & 7))) << 4);
            if (idx < 512) CP_ASYNC16(bh + doff, ehp + e*16);
            else           CP_ASYNC16(bl + doff, elp + e*16);
        }
        CP_COMMIT();
    }
    ((float4*)(vsmem + VQ_E2))[t] = ((const float4*)g_e2)[t];
    __syncthreads();

    {
        float* pool = (float*)(vsmem + VQ_POOL);
        uint4* ah4 = (uint4*)(vsmem + VQ_AHI);
        uint4* al4 = (uint4*)(vsmem + VQ_ALO);
#pragma unroll
        for (int j = 0; j < 2; j++) {
            int e8 = t + j*256;
            int r = e8 >> 3, c8 = e8 & 7;
            int k0 = c8*8;
            const float4* pr = (const float4*)(g_praw + (size_t)(row0 + r)*64 + k0);
            float4 v0 = pr[0], v1 = pr[1];
            float vv[8] = {v0.x, v0.y, v0.z, v0.w, v1.x, v1.y, v1.z, v1.w};
            unsigned hh[8], ll[8];
#pragma unroll
            for (int i = 0; i < 8; i++) {
                float vb = fmaxf(fmaf(vv[i], s_ss[(k0+i)*2], s_ss[(k0+i)*2+1]), 0.f);
                vv[i] = vb;
                __nv_bfloat16 h = __float2bfloat16(vb);
                hh[i] = __bfloat16_as_ushort(h);
                ll[i] = __bfloat16_as_ushort(__float2bfloat16(vb - __bfloat162float(h)));
            }
            float* pp = pool + r*68 + k0;
            ((float4*)pp)[0] = make_float4(vv[0], vv[1], vv[2], vv[3]);
            ((float4*)pp)[1] = make_float4(vv[4], vv[5], vv[6], vv[7]);
            int dst = r*8 + (c8 ^ (r & 7));
            uint4 H, L;
            H.x = (hh[1]<<16)|hh[0]; H.y = (hh[3]<<16)|hh[2];
            H.z = (hh[5]<<16)|hh[4]; H.w = (hh[7]<<16)|hh[6];
            L.x = (ll[1]<<16)|ll[0]; L.y = (ll[3]<<16)|ll[2];
            L.z = (ll[5]<<16)|ll[4]; L.w = (ll[7]<<16)|ll[6];
            ah4[dst] = H;
            al4[dst] = L;
        }
    }
    CP_WAIT0();
    __syncthreads();

    unsigned int afrag[2][2][4][4];
    {
        unsigned int aHiB = uBase + VQ_AHI;
        unsigned int aLoB = uBase + VQ_ALO;
        int ahalf = lane >> 4;
#pragma unroll
        for (int rt2 = 0; rt2 < 2; rt2++) {
            int ar = rt*32 + rt2*16 + (lane & 15);
#pragma unroll
            for (int ks = 0; ks < 4; ks++) {
                unsigned int off = (unsigned int)(ar*128 + (((ks*2 + ahalf) ^ (ar & 7)) << 4));
                LDSM_X4(afrag[0][rt2][ks][0], afrag[0][rt2][ks][1], afrag[0][rt2][ks][2], afrag[0][rt2][ks][3], aHiB + off);
                LDSM_X4(afrag[1][rt2][ks][0], afrag[1][rt2][ks][1], afrag[1][rt2][ks][2], afrag[1][rt2][ks][3], aLoB + off);
            }
        }
    }

    const float* sE2 = (const float*)(vsmem + VQ_E2);
    const float INF = __int_as_float(0x7f800000);
    float kk1[2][2], kk2[2][2];
#pragma unroll
    for (int i = 0; i < 2; i++)
#pragma unroll
        for (int j = 0; j < 2; j++) { kk1[i][j] = INF; kk2[i][j] = INF; }

    int brow = cq*16 + (lane >> 4)*8 + (lane & 7);
    int bkhalf = (lane >> 3) & 1;

    for (int ch = 0; ch < 16; ch++) {
        int cur = ch & 1;
        if (ch + 1 < 16) {
            unsigned int bh = uBase + (cur ? VQ_B0H : VQ_B1H);
            unsigned int bl = uBase + (cur ? VQ_B0L : VQ_B1L);
            const char* sh = ehp + (ch+1)*8192;
            const char* sl = elp + (ch+1)*8192;
#pragma unroll
            for (int j = 0; j < 4; j++) {
                int idx = t + j*256;
                int e = idx & 511;
                int r = e >> 3, kc = e & 7;
                unsigned int doff = (unsigned int)((r*8 + (kc ^ (r & 7))) << 4);
                if (idx < 512) CP_ASYNC16(bh + doff, sh + e*16);
                else           CP_ASYNC16(bl + doff, sl + e*16);
            }
            CP_COMMIT();
        }

        unsigned int eHiB = uBase + (cur ? VQ_B1H : VQ_B0H);
        unsigned int eLoB = uBase + (cur ? VQ_B1L : VQ_B0L);

        float acc[2][2][4];
#pragma unroll
        for (int i = 0; i < 2; i++)
#pragma unroll
            for (int j = 0; j < 2; j++)
#pragma unroll
                for (int q = 0; q < 4; q++) acc[i][j][q] = 0.f;

#pragma unroll
        for (int ks = 0; ks < 4; ks++) {
            int kc = ks*2 + bkhalf;
            unsigned int off = (unsigned int)(brow*128 + ((kc ^ (brow & 7)) << 4));
            unsigned int bh0, bh1, bh2, bh3, bl0, bl1, bl2, bl3;
            LDSM_X4(bh0, bh1, bh2, bh3, eHiB + off);
            LDSM_X4(bl0, bl1, bl2, bl3, eLoB + off);
            MMA16816(acc[0][0], afrag[0][0][ks][0], afrag[0][0][ks][1], afrag[0][0][ks][2], afrag[0][0][ks][3], bh0, bh1);
            MMA16816(acc[0][1], afrag[0][0][ks][0], afrag[0][0][ks][1], afrag[0][0][ks][2], afrag[0][0][ks][3], bh2, bh3);
            MMA16816(acc[1][0], afrag[0][1][ks][0], afrag[0][1][ks][1], afrag[0][1][ks][2], afrag[0][1][ks][3], bh0, bh1);
            MMA16816(acc[1][1], afrag[0][1][ks][0], afrag[0][1][ks][1], afrag[0][1][ks][2], afrag[0][1][ks][3], bh2, bh3);
            MMA16816(acc[0][0], afrag[0][0][ks][0], afrag[0][0][ks][1], afrag[0][0][ks][2], afrag[0][0][ks][3], bl0, bl1);
            MMA16816(acc[0][1], afrag[0][0][ks][0], afrag[0][0][ks][1], afrag[0][0][ks][2], afrag[0][0][ks][3], bl2, bl3);
            MMA16816(acc[1][0], afrag[0][1][ks][0], afrag[0][1][ks][1], afrag[0][1][ks][2], afrag[0][1][ks][3], bl0, bl1);
            MMA16816(acc[1][1], afrag[0][1][ks][0], afrag[0][1][ks][1], afrag[0][1][ks][2], afrag[0][1][ks][3], bl2, bl3);
            MMA16816(acc[0][0], afrag[1][0][ks][0], afrag[1][0][ks][1], afrag[1][0][ks][2], afrag[1][0][ks][3], bh0, bh1);
            MMA16816(acc[0][1], afrag[1][0][ks][0], afrag[1][0][ks][1], afrag[1][0][ks][2], afrag[1][0][ks][3], bh2, bh3);
            MMA16816(acc[1][0], afrag[1][1][ks][0], afrag[1][1][ks][1], afrag[1][1][ks][2], afrag[1][1][ks][3], bh0, bh1);
            MMA16816(acc[1][1], afrag[1][1][ks][0], afrag[1][1][ks][1], afrag[1][1][ks][2], afrag[1][1][ks][3], bh2, bh3);
        }

        int cb = ch*64 + cq*16 + (lane & 3)*2;
#pragma unroll
        for (int rt2 = 0; rt2 < 2; rt2++) {
#pragma unroll
            for (int ct = 0; ct < 2; ct++) {
                int c0 = cb + ct*8, c1 = c0 + 1;
                float e20 = sE2[c0], e21 = sE2[c1];
                float dA0 = fmaf(-2.f, acc[rt2][ct][0], e20);
                float dA1 = fmaf(-2.f, acc[rt2][ct][1], e21);
                float dB0 = fmaf(-2.f, acc[rt2][ct][2], e20);
                float dB1 = fmaf(-2.f, acc[rt2][ct][3], e21);
                float kA0 = __uint_as_float((__float_as_uint(dA0) & 0xFFFFFC00u) | (unsigned)c0);
                float kA1 = __uint_as_float((__float_as_uint(dA1) & 0xFFFFFC00u) | (unsigned)c1);
                float kB0 = __uint_as_float((__float_as_uint(dB0) & 0xFFFFFC00u) | (unsigned)c0);
                float kB1 = __uint_as_float((__float_as_uint(dB1) & 0xFFFFFC00u) | (unsigned)c1);
                float hi;
                hi = fmaxf(kk1[rt2][0], kA0); kk1[rt2][0] = fminf(kk1[rt2][0], kA0); kk2[rt2][0] = fminf(kk2[rt2][0], hi);
                hi = fmaxf(kk1[rt2][0], kA1); kk1[rt2][0] = fminf(kk1[rt2][0], kA1); kk2[rt2][0] = fminf(kk2[rt2][0], hi);
                hi = fmaxf(kk1[rt2][1], kB0); kk1[rt2][1] = fminf(kk1[rt2][1], kB0); kk2[rt2][1] = fminf(kk2[rt2][1], hi);
                hi = fmaxf(kk1[rt2][1], kB1); kk1[rt2][1] = fminf(kk1[rt2][1], kB1); kk2[rt2][1] = fminf(kk2[rt2][1], hi);
            }
        }

        if (ch + 1 < 16) CP_WAIT0();
        __syncthreads();
    }

    const unsigned FULL = 0xffffffffu;
#pragma unroll
    for (int off = 2; off > 0; off >>= 1) {
#pragma unroll
        for (int rt2 = 0; rt2 < 2; rt2++)
#pragma unroll
            for (int s = 0; s < 2; s++) {
                float o1 = __shfl_down_sync(FULL, kk1[rt2][s], off, 4);
                float o2 = __shfl_down_sync(FULL, kk2[rt2][s], off, 4);
                float hi = fmaxf(kk1[rt2][s], o1);
                kk1[rt2][s] = fminf(kk1[rt2][s], o1);
                kk2[rt2][s] = fminf(fminf(kk2[rt2][s], o2), hi);
            }
    }

    float* k1buf = (float*)(vsmem + VQ_B0H);
    float* k2buf = (float*)(vsmem + VQ_B0H + 1024);
    int* s_b1 = (int*)(vsmem + VQ_B0H + 2048);
    if ((lane & 3) == 0) {
        int g = lane >> 2;
#pragma unroll
        for (int rt2 = 0; rt2 < 2; rt2++) {
            int rA = rt*32 + rt2*16 + g;
            k1buf[rA*4 + cq]     = kk1[rt2][0];
            k2buf[rA*4 + cq]     = kk2[rt2][0];
            k1buf[(rA+8)*4 + cq] = kk1[rt2][1];
            k2buf[(rA+8)*4 + cq] = kk2[rt2][1];
        }
    }
    __syncthreads();

    const float* pool = (const float*)(vsmem + VQ_POOL);
    if (t < 64) {
        float m1 = INF;
#pragma unroll
        for (int q = 0; q < 4; q++) m1 = fminf(m1, k1buf[t*4 + q]);
        float m2 = INF;
#pragma unroll
        for (int q = 0; q < 4; q++) {
            float v1 = k1buf[t*4 + q], v2 = k2buf[t*4 + q];
            m2 = fminf(m2, (v1 > m1) ? v1 : INF);
            m2 = fminf(m2, (v2 > m1) ? v2 : INF);
        }
        int i1 = (int)(__float_as_uint(m1) & 1023u);
        int i2 = (int)(__float_as_uint(m2) & 1023u);
        int best = i1;
        if (i2 != i1) {
            const float4* frow = (const float4*)(pool + t*68);
            const float4* ea = (const float4*)(embed + (size_t)i1*64);
            const float4* eb = (const float4*)(embed + (size_t)i2*64);
            float da = 0.f, db = 0.f;
#pragma unroll
            for (int k = 0; k < 16; k++) {
                float4 f = frow[k], va = ea[k], vb = eb[k];
                da = fmaf(f.x, va.x, da); da = fmaf(f.y, va.y, da);
                da = fmaf(f.z, va.z, da); da = fmaf(f.w, va.w, da);
                db = fmaf(f.x, vb.x, db); db = fmaf(f.y, vb.y, db);
                db = fmaf(f.z, vb.z, db); db = fmaf(f.w, vb.w, db);
            }
            float dda = fmaf(-2.f, da, sE2[i1]);
            float ddb = fmaf(-2.f, db, sE2[i2]);
            if (better(ddb, i2, dda, i1)) best = i2;
        }
        s_b1[t] = best;
        g_idx[row0 + t] = best;
        out[YELEMS + row0 + t] = (float)best;
    }
    __syncthreads();

    float lacc = 0.f;
#pragma unroll
    for (int it = 0; it < 16; it++) {
        int e = it*256 + t;
        int r = e >> 6, d = e & 63;
        int ci = s_b1[r];
        float qv = embed[ci*64 + d];
        float fv = pool[r*68 + d];
        float df = qv - fv;
        lacc = fmaf(df, df, lacc);
    }

    float* s_red = (float*)(vsmem + VQ_B1H);
    s_red[t] = lacc;
    __syncthreads();
    for (int o = 128; o > 0; o >>= 1) {
        if (t < o) s_red[t] += s_red[t+o];
        __syncthreads();
    }
    if (t == 0) g_losspart[blockIdx.x] = s_red[0];
}

// ============================================================
// decoder: nearest-x2 upsample fused with conv2 (collapsed 2x2),
// quant gathered from embed via g_idx + FUSED BN2 stats.
// ============================================================
#define DCK 16
__global__ void __launch_bounds__(256) conv2up_k(const float* __restrict__ embed,
                                                 const float* __restrict__ bias)
{
    __shared__ float s_q[DCK][18][34];
    __shared__ float s_cw[48][DCK];
    __shared__ int s_ci[612];
    __shared__ float s_st[3][8][2];
    int t = threadIdx.x;
    int tx = t & 15, ty = t >> 4;
    int wid = t >> 5, lane = t & 31;
    int x0 = blockIdx.x*32, y0 = blockIdx.y*16, bb = blockIdx.z;
    int bid2 = (bb*8 + blockIdx.y)*4 + blockIdx.x;   // 0..255

    for (int e = t; e < 612; e += 256) {
        int r = e / 34, c = e % 34;
        int qy = y0 - 1 + r, qx = x0 - 1 + c;
        int ci = -1;
        if (qy >= 0 && qy < 128 && qx >= 0 && qx < 128)
            ci = g_idx[(bb*128 + qy)*128 + qx];
        s_ci[e] = ci;
    }

    float acc[2][2][2][3];
#pragma unroll
    for (int a1 = 0; a1 < 2; a1++)
#pragma unroll
        for (int a2 = 0; a2 < 2; a2++)
#pragma unroll
            for (int a3 = 0; a3 < 2; a3++)
#pragma unroll
                for (int a4 = 0; a4 < 3; a4++) acc[a1][a2][a3][a4] = 0.f;

    for (int ch = 0; ch < 64/DCK; ch++) {
        __syncthreads();
        for (int e = t; e < 48*DCK; e += 256) {
            int row = e >> 4, dl = e & (DCK-1);
            s_cw[row][dl] = g_cw[row*64 + ch*DCK + dl];
        }
        for (int e = t; e < 612*DCK; e += 256) {
            int dl = e & (DCK-1);
            int cell = e >> 4;
            int ci = s_ci[cell];
            float v = (ci >= 0) ? embed[ci*64 + ch*DCK + dl] : 0.f;
            s_q[dl][cell / 34][cell % 34] = v;
        }
        __syncthreads();

#pragma unroll 4
        for (int dl = 0; dl < DCK; dl++) {
            float qv[3][4];
#pragma unroll
            for (int a = 0; a < 3; a++)
#pragma unroll
                for (int c = 0; c < 4; c++)
                    qv[a][c] = s_q[dl][ty + a][2*tx + c];
#pragma unroll
            for (int co = 0; co < 3; co++)
#pragma unroll
                for (int py = 0; py < 2; py++)
#pragma unroll
                    for (int px = 0; px < 2; px++) {
#pragma unroll
                        for (int ty_ = 0; ty_ < 2; ty_++)
#pragma unroll
                            for (int tx_ = 0; tx_ < 2; tx_++) {
                                float wv = s_cw[((py*2+px)*3+co)*4 + ty_*2+tx_][dl];
#pragma unroll
                                for (int xi = 0; xi < 2; xi++)
                                    acc[xi][py][px][co] =
                                        fmaf(qv[py+ty_][xi+px+tx_], wv, acc[xi][py][px][co]);
                            }
                    }
        }
    }

    // store + fused BN2 stats
    const unsigned FULL = 0xffffffffu;
    int qy = y0 + ty;
    float ls[3], lq[3];
#pragma unroll
    for (int co = 0; co < 3; co++) { ls[co] = 0.f; lq[co] = 0.f; }
#pragma unroll
    for (int co = 0; co < 3; co++) {
        float bv = bias[co];
#pragma unroll
        for (int xi = 0; xi < 2; xi++) {
            int qx = x0 + 2*tx + xi;
#pragma unroll
            for (int py = 0; py < 2; py++)
#pragma unroll
                for (int px = 0; px < 2; px++) {
                    int Y = 2*qy + py, X = 2*qx + px;
                    float v = acc[xi][py][px][co] + bv;
                    g_y2[((bb*3 + co) << 16) + (Y << 8) + X] = v;
                    ls[co] += v;
                    lq[co] = fmaf(v, v, lq[co]);
                }
        }
    }
#pragma unroll
    for (int co = 0; co < 3; co++) {
#pragma unroll
        for (int o = 16; o > 0; o >>= 1) {
            ls[co] += __shfl_xor_sync(FULL, ls[co], o);
            lq[co] += __shfl_xor_sync(FULL, lq[co], o);
        }
        if (lane == 0) { s_st[co][wid][0] = ls[co]; s_st[co][wid][1] = lq[co]; }
    }
    __syncthreads();
    if (t < 3) {
        float S = 0.f, Q = 0.f;
#pragma unroll
        for (int i = 0; i < 8; i++) { S += s_st[t][i][0]; Q += s_st[t][i][1]; }
        g_part2[(t*256 + bid2)*2]     = S;
        g_part2[(t*256 + bid2)*2 + 1] = Q;
    }
}

// finalize BN2 (256 partials/channel) + loss output
__global__ void __launch_bounds__(256) fin2loss_k(const float* __restrict__ gamma,
                                                  const float* __restrict__ beta,
                                                  float* __restrict__ out)
{
    int t = threadIdx.x;
    if (t < 3) {
        float sum = 0.f, sq = 0.f;
        for (int s = 0; s < 256; s++) { sum += g_part2[(t*256+s)*2]; sq += g_part2[(t*256+s)*2+1]; }
        float inv = 1.f / (float)BNCNT;
        float mean = sum * inv;
        float var = sq * inv - mean*mean;
        float scale = gamma[t] * rsqrtf(var + EPSBN);
        g_bn2[t*2]   = scale;
        g_bn2[t*2+1] = beta[t] - mean*scale;
    }
    __shared__ float s[256];
    float acc = 0.f;
#pragma unroll
    for (int j = 0; j < 8; j++) acc += g_losspart[t + j*256];
    s[t] = acc;
    __syncthreads();
    for (int o = 128; o > 0; o >>= 1) {
        if (t < o) s[t] += s[t+o];
        __syncthreads();
    }
    if (t == 0) out[YELEMS + NPTS] = 0.25f * s[0] / (float)(NPTS * DD);
}

// ============================================================
// BN2 apply + tanh -> d_out (float4)
// ============================================================
__global__ void __launch_bounds__(256) bn2tanh_k(float* __restrict__ out)
{
    int e4 = blockIdx.x*256 + threadIdx.x;
    int c = (e4 >> 14) % 3;
    float sc = g_bn2[c*2], sh = g_bn2[c*2+1];
    float4 v = ((const float4*)g_y2)[e4];
    float4 r;
    r.x = tanhf(fmaf(v.x, sc, sh));
    r.y = tanhf(fmaf(v.y, sc, sh));
    r.z = tanhf(fmaf(v.z, sc, sh));
    r.w = tanhf(fmaf(v.w, sc, sh));
    ((float4*)out)[e4] = r;
}

// ============================================================
extern "C" void kernel_launch(void* const* d_in, const int* in_sizes, int n_in,
                              void* d_out, int out_size)
{
    const float* x   = (const float*)d_in[0];
    const float* w1  = (const float*)d_in[1];
    const float* b1  = (const float*)d_in[2];
    const float* g1  = (const float*)d_in[3];
    const float* be1 = (const float*)d_in[4];
    const float* em  = (const float*)d_in[5];
    const float* w2  = (const float*)d_in[6];
    const float* b2  = (const float*)d_in[7];
    const float* g2  = (const float*)d_in[8];
    const float* be2 = (const float*)d_in[9];
    float* out = (float*)d_out;
    (void)in_sizes; (void)n_in; (void)out_size;

    const int POOL_SMEM = 16*16*65*4;   // 66560
    cudaFuncSetAttribute(conv1pool_k, cudaFuncAttributeMaxDynamicSharedMemorySize, POOL_SMEM);
    cudaFuncSetAttribute(vq_k, cudaFuncAttributeMaxDynamicSharedMemorySize, VQ_SMEM_SZ);

    conv1pool_k<<<dim3(8,8,4), dim3(32,8), POOL_SMEM>>>(x, w1, b1); // 0
    finalize1_k<<<64, 256>>>(g1, be1);                              // 1
    prep2_k<<<140, 256>>>(em, w2);                                  // 2
    vq_k<<<NPTS/64, 256, VQ_SMEM_SZ>>>(em, out);                    // 3  <- profiled
    conv2up_k<<<dim3(4,8,8), 256>>>(em, b2);                        // 4  (stats fused)
    fin2loss_k<<<1, 256>>>(g2, be2, out);                           // 5
    bn2tanh_k<<<YELEMS/1024, 256>>>(out);                           // 6
}

// round 14
// speedup vs baseline: 1.0411x; 1.0411x over previous
#include <cuda_runtime.h>
#include <cuda_bf16.h>
#include <cstdint>
#include <math.h>

#define EPSBN 1e-5f

#define NB 8
#define CIN 3
#define HIMG 256
#define WIMG 256
#define DD 64
#define KC 1024
#define HP 128
#define WP 128
#define NPTS (NB*HP*WP)            /* 131072 */
#define YELEMS (NB*CIN*HIMG*WIMG)  /* 1572864 */
#define BNCNT (NB*HIMG*WIMG)       /* 524288 per channel */

// ---------------- scratch (device globals; allocation-free) ----------------
__device__ float g_praw[NPTS*DD];
__device__ __align__(16) __nv_bfloat16 g_ehi[KC*DD];
__device__ __align__(16) __nv_bfloat16 g_elo[KC*DD];
__device__ int   g_idx[NPTS];
__device__ float g_y2[YELEMS];
__device__ __align__(16) float g_e2[KC];
__device__ float g_cw[48*64];
__device__ float g_part1[64*512*2];
__device__ float g_part2[3*32*2];
__device__ float g_bn1[64*2];
__device__ float g_bn2[3*2];
__device__ float g_losspart[2048];

// ---------------- mma / async helpers ----------------
#define LDSM_X4(r0,r1,r2,r3,addr) \
    asm volatile("ldmatrix.sync.aligned.m8n8.x4.shared.b16 {%0,%1,%2,%3},[%4];" \
        : "=r"(r0),"=r"(r1),"=r"(r2),"=r"(r3) : "r"(addr))
#define MMA16816(c,a0,a1,a2,a3,b0,b1) \
    asm volatile("mma.sync.aligned.m16n8k16.row.col.f32.bf16.bf16.f32 " \
        "{%0,%1,%2,%3},{%4,%5,%6,%7},{%8,%9},{%0,%1,%2,%3};" \
        : "+f"((c)[0]),"+f"((c)[1]),"+f"((c)[2]),"+f"((c)[3]) \
        : "r"(a0),"r"(a1),"r"(a2),"r"(a3),"r"(b0),"r"(b1))
#define CP_ASYNC16(dst, src) \
    asm volatile("cp.async.ca.shared.global [%0], [%1], 16;" \
        :: "r"(dst), "l"(src) : "memory")
#define CP_COMMIT() asm volatile("cp.async.commit_group;" ::: "memory")
#define CP_WAIT0()  asm volatile("cp.async.wait_group 0;" ::: "memory")

__device__ __forceinline__ bool better(float da, int ia, float db, int ib) {
    return da < db || (da == db && ia < ib);
}

// ============================================================
// conv1 + bias + fused BN1 stats + fused maxpool2
// occ-3 version: half-size pool staging [16][16][33], co in 2 halves
// ============================================================
#define C1_SMEM (16*16*33*4)   /* 33792 */
__global__ void __launch_bounds__(256,3) conv1pool_k(const float* __restrict__ x,
                                                     const float* __restrict__ w,
                                                     const float* __restrict__ bias)
{
    __shared__ float s_in[3][34][34];
    __shared__ float s_w[64*27];
    __shared__ float s_b[64];
    __shared__ float s_sum[64*8];
    __shared__ float s_sq[64*8];
    extern __shared__ float s_pool[];   // [16][16][33]

    int tx = threadIdx.x, ty = threadIdx.y;
    int tid = ty*32 + tx;
    int wid = tid >> 5;
    int lane = tid & 31;
    int x0 = blockIdx.x*32, y0 = blockIdx.y*32, b = blockIdx.z;
    int bid = (b*8 + blockIdx.y)*8 + blockIdx.x;

    for (int i = tid; i < 64*27; i += 256) s_w[i] = w[i];
    if (tid < 64) s_b[tid] = bias[tid];
    for (int i = tid; i < 3*34*34; i += 256) {
        int c = i / (34*34); int r = i % (34*34);
        int yy = r / 34, xx = r % 34;
        int gy = y0 + yy - 1, gx = x0 + xx - 1;
        float v = 0.f;
        if (gy >= 0 && gy < 256 && gx >= 0 && gx < 256)
            v = x[((b*3 + c)*256 + gy)*256 + gx];
        s_in[c][yy][xx] = v;
    }
    __syncthreads();

    float rin[3][6][3];
#pragma unroll
    for (int c = 0; c < 3; c++)
#pragma unroll
        for (int r = 0; r < 6; r++)
#pragma unroll
            for (int q = 0; q < 3; q++)
                rin[c][r][q] = s_in[c][ty*4 + r][tx + q];

    const unsigned FULL = 0xffffffffu;
    int pxl = tx >> 1;
    int pr0 = ty*2;

    for (int h = 0; h < 2; h++) {
        if (h) __syncthreads();    // prior half's s_pool reads complete
        for (int co2 = 0; co2 < 32; co2++) {
            int co = h*32 + co2;
            float bb = s_b[co];
            float a0 = bb, a1 = bb, a2 = bb, a3 = bb;
#pragma unroll
            for (int c = 0; c < 3; c++)
#pragma unroll
                for (int ky = 0; ky < 3; ky++)
#pragma unroll
                    for (int kx = 0; kx < 3; kx++) {
                        float wv = s_w[co*27 + c*9 + ky*3 + kx];
                        a0 = fmaf(rin[c][0+ky][kx], wv, a0);
                        a1 = fmaf(rin[c][1+ky][kx], wv, a1);
                        a2 = fmaf(rin[c][2+ky][kx], wv, a2);
                        a3 = fmaf(rin[c][3+ky][kx], wv, a3);
                    }
            float s = a0 + a1 + a2 + a3;
            float q = a0*a0; q = fmaf(a1,a1,q); q = fmaf(a2,a2,q); q = fmaf(a3,a3,q);
#pragma unroll
            for (int o = 16; o > 0; o >>= 1) {
                s += __shfl_xor_sync(FULL, s, o);
                q += __shfl_xor_sync(FULL, q, o);
            }
            if (lane == 0) { s_sum[co*8 + wid] = s; s_sq[co*8 + wid] = q; }
            float m0 = fmaxf(a0, a1);
            float m1 = fmaxf(a2, a3);
            m0 = fmaxf(m0, __shfl_xor_sync(FULL, m0, 1));
            m1 = fmaxf(m1, __shfl_xor_sync(FULL, m1, 1));
            if ((tx & 1) == 0) {
                s_pool[(pr0*16 + pxl)*33 + co2]     = m0;
                s_pool[((pr0+1)*16 + pxl)*33 + co2] = m1;
            }
        }
        __syncthreads();

        int base = (((b*128 + (y0 >> 1))*128) + (x0 >> 1))*64 + h*32;
        for (int i = tid; i < 8192; i += 256) {
            int r = i >> 9, j = i & 511;
            int px = j >> 5, c = j & 31;
            g_praw[base + r*8192 + px*64 + c] = s_pool[(r*16 + px)*33 + c];
        }
    }

    if (tid < 64) {
        float S = 0.f, Q = 0.f;
#pragma unroll
        for (int i = 0; i < 8; i++) { S += s_sum[tid*8 + i]; Q += s_sq[tid*8 + i]; }
        g_part1[(tid*512 + bid)*2]     = S;
        g_part1[(tid*512 + bid)*2 + 1] = Q;
    }
}

// ============================================================
// finalize BN1 (one block per channel)
// ============================================================
__global__ void __launch_bounds__(256) finalize1_k(const float* __restrict__ gamma,
                                                   const float* __restrict__ beta)
{
    int c = blockIdx.x, t = threadIdx.x;
    float s = 0.f, q = 0.f;
    for (int i = t; i < 512; i += 256) {
        s += g_part1[(c*512 + i)*2];
        q += g_part1[(c*512 + i)*2 + 1];
    }
    __shared__ float ss[256], s2[256];
    ss[t] = s; s2[t] = q; __syncthreads();
    for (int o = 128; o > 0; o >>= 1) {
        if (t < o) { ss[t] += ss[t+o]; s2[t] += s2[t+o]; }
        __syncthreads();
    }
    if (t == 0) {
        float inv = 1.f / (float)BNCNT;
        float mean = ss[0] * inv;
        float var = s2[0] * inv - mean*mean;
        float scale = gamma[c] * rsqrtf(var + EPSBN);
        g_bn1[c*2]   = scale;
        g_bn1[c*2+1] = beta[c] - mean*scale;
    }
}

// ============================================================
// prep2: embed bf16 split + ||e||^2 (blocks 0-127), conv2 weight
// collapse (blocks 128-139)
// ============================================================
__global__ void __launch_bounds__(256) prep2_k(const float* __restrict__ embed,
                                               const float* __restrict__ w2)
{
    int bb = blockIdx.x;
    int t = threadIdx.x;
    if (bb < 128) {
        int code = bb*8 + (t >> 5);
        int lane = t & 31;
        float a = embed[code*64 + lane];
        float b2v = embed[code*64 + 32 + lane];
        __nv_bfloat16 ah = __float2bfloat16(a);
        __nv_bfloat16 bh = __float2bfloat16(b2v);
        g_ehi[code*64 + lane] = ah;
        g_ehi[code*64 + 32 + lane] = bh;
        g_elo[code*64 + lane] = __float2bfloat16(a - __bfloat162float(ah));
        g_elo[code*64 + 32 + lane] = __float2bfloat16(b2v - __bfloat162float(bh));
        float s = a*a + b2v*b2v;
#pragma unroll
        for (int o = 16; o > 0; o >>= 1)
            s += __shfl_down_sync(0xffffffffu, s, o);
        if (lane == 0) g_e2[code] = s;
    } else {
        int e = (bb - 128)*256 + t;
        if (e < 48*64) {
            int d = e & 63;
            int rest = e >> 6;
            int tap = rest & 3;
            int tx_ = tap & 1, ty_ = tap >> 1;
            int co = (rest >> 2) % 3;
            int ph = rest / 12;
            int px = ph & 1, py = ph >> 1;
            float s = 0.f;
            for (int ky = 0; ky < 3; ky++) {
                int mapy = (py == 0) ? ((ky == 0) ? 0 : 1) : ((ky < 2) ? 0 : 1);
                if (mapy != ty_) continue;
                for (int kx = 0; kx < 3; kx++) {
                    int mapx = (px == 0) ? ((kx == 0) ? 0 : 1) : ((kx < 2) ? 0 : 1);
                    if (mapx != tx_) continue;
                    s += w2[((co*64 + d)*3 + ky)*3 + kx];
                }
            }
            g_cw[e] = s;
        }
    }
}

// ============================================================
// VQ: fused BN+ReLU+bf16-split of A (from g_praw) + hi/lo 3-GEMM
// via mma.sync with cp.async double-buffered B (1 sync/chunk).
// Packed-key top-2 + exact fp32 refine. Writes indices only.
// ============================================================
#define VQ_AHI  0
#define VQ_ALO  8192
#define VQ_POOL 16384
#define VQ_B0H  33792
#define VQ_B0L  41984
#define VQ_B1H  50176
#define VQ_B1L  58368
#define VQ_E2   66560
#define VQ_SMEM_SZ 70656

__global__ void __launch_bounds__(256,2) vq_k(const float* __restrict__ embed,
                                              float* __restrict__ out)
{
    extern __shared__ __align__(16) char vsmem[];
    __shared__ float s_ss[128];
    int t = threadIdx.x;
    int w = t >> 5, lane = t & 31;
    int rt = w & 1;
    int cq = w >> 1;
    int row0 = blockIdx.x * 64;
    unsigned int uBase = (unsigned int)__cvta_generic_to_shared(vsmem);
    const char* ehp = (const char*)g_ehi;
    const char* elp = (const char*)g_elo;

    if (t < 128) s_ss[t] = g_bn1[t];

    {
        unsigned int bh = uBase + VQ_B0H;
        unsigned int bl = uBase + VQ_B0L;
#pragma unroll
        for (int j = 0; j < 4; j++) {
            int idx = t + j*256;
            int e = idx & 511;
            int r = e >> 3, kc = e & 7;
            unsigned int doff = (unsigned int)((r*8 + (kc ^ (r & 7))) << 4);
            if (idx < 512) CP_ASYNC16(bh + doff, ehp + e*16);
            else           CP_ASYNC16(bl + doff, elp + e*16);
        }
        CP_COMMIT();
    }
    ((float4*)(vsmem + VQ_E2))[t] = ((const float4*)g_e2)[t];
    __syncthreads();

    {
        float* pool = (float*)(vsmem + VQ_POOL);
        uint4* ah4 = (uint4*)(vsmem + VQ_AHI);
        uint4* al4 = (uint4*)(vsmem + VQ_ALO);
#pragma unroll
        for (int j = 0; j < 2; j++) {
            int e8 = t + j*256;
            int r = e8 >> 3, c8 = e8 & 7;
            int k0 = c8*8;
            const float4* pr = (const float4*)(g_praw + (size_t)(row0 + r)*64 + k0);
            float4 v0 = pr[0], v1 = pr[1];
            float vv[8] = {v0.x, v0.y, v0.z, v0.w, v1.x, v1.y, v1.z, v1.w};
            unsigned hh[8], ll[8];
#pragma unroll
            for (int i = 0; i < 8; i++) {
                float vb = fmaxf(fmaf(vv[i], s_ss[(k0+i)*2], s_ss[(k0+i)*2+1]), 0.f);
                vv[i] = vb;
                __nv_bfloat16 hb = __float2bfloat16(vb);
                hh[i] = __bfloat16_as_ushort(hb);
                ll[i] = __bfloat16_as_ushort(__float2bfloat16(vb - __bfloat162float(hb)));
            }
            float* pp = pool + r*68 + k0;
            ((float4*)pp)[0] = make_float4(vv[0], vv[1], vv[2], vv[3]);
            ((float4*)pp)[1] = make_float4(vv[4], vv[5], vv[6], vv[7]);
            int dst = r*8 + (c8 ^ (r & 7));
            uint4 H, L;
            H.x = (hh[1]<<16)|hh[0]; H.y = (hh[3]<<16)|hh[2];
            H.z = (hh[5]<<16)|hh[4]; H.w = (hh[7]<<16)|hh[6];
            L.x = (ll[1]<<16)|ll[0]; L.y = (ll[3]<<16)|ll[2];
            L.z = (ll[5]<<16)|ll[4]; L.w = (ll[7]<<16)|ll[6];
            ah4[dst] = H;
            al4[dst] = L;
        }
    }
    CP_WAIT0();
    __syncthreads();

    unsigned int afrag[2][2][4][4];
    {
        unsigned int aHiB = uBase + VQ_AHI;
        unsigned int aLoB = uBase + VQ_ALO;
        int ahalf = lane >> 4;
#pragma unroll
        for (int rt2 = 0; rt2 < 2; rt2++) {
            int ar = rt*32 + rt2*16 + (lane & 15);
#pragma unroll
            for (int ks = 0; ks < 4; ks++) {
                unsigned int off = (unsigned int)(ar*128 + (((ks*2 + ahalf) ^ (ar & 7)) << 4));
                LDSM_X4(afrag[0][rt2][ks][0], afrag[0][rt2][ks][1], afrag[0][rt2][ks][2], afrag[0][rt2][ks][3], aHiB + off);
                LDSM_X4(afrag[1][rt2][ks][0], afrag[1][rt2][ks][1], afrag[1][rt2][ks][2], afrag[1][rt2][ks][3], aLoB + off);
            }
        }
    }

    const float* sE2 = (const float*)(vsmem + VQ_E2);
    const float INF = __int_as_float(0x7f800000);
    float kk1[2][2], kk2[2][2];
#pragma unroll
    for (int i = 0; i < 2; i++)
#pragma unroll
        for (int j = 0; j < 2; j++) { kk1[i][j] = INF; kk2[i][j] = INF; }

    int brow = cq*16 + (lane >> 4)*8 + (lane & 7);
    int bkhalf = (lane >> 3) & 1;

    for (int ch = 0; ch < 16; ch++) {
        int cur = ch & 1;
        if (ch + 1 < 16) {
            unsigned int bh = uBase + (cur ? VQ_B0H : VQ_B1H);
            unsigned int bl = uBase + (cur ? VQ_B0L : VQ_B1L);
            const char* sh = ehp + (ch+1)*8192;
            const char* sl = elp + (ch+1)*8192;
#pragma unroll
            for (int j = 0; j < 4; j++) {
                int idx = t + j*256;
                int e = idx & 511;
                int r = e >> 3, kc = e & 7;
                unsigned int doff = (unsigned int)((r*8 + (kc ^ (r & 7))) << 4);
                if (idx < 512) CP_ASYNC16(bh + doff, sh + e*16);
                else           CP_ASYNC16(bl + doff, sl + e*16);
            }
            CP_COMMIT();
        }

        unsigned int eHiB = uBase + (cur ? VQ_B1H : VQ_B0H);
        unsigned int eLoB = uBase + (cur ? VQ_B1L : VQ_B0L);

        float acc[2][2][4];
#pragma unroll
        for (int i = 0; i < 2; i++)
#pragma unroll
            for (int j = 0; j < 2; j++)
#pragma unroll
                for (int q = 0; q < 4; q++) acc[i][j][q] = 0.f;

#pragma unroll
        for (int ks = 0; ks < 4; ks++) {
            int kc = ks*2 + bkhalf;
            unsigned int off = (unsigned int)(brow*128 + ((kc ^ (brow & 7)) << 4));
            unsigned int bh0, bh1, bh2, bh3, bl0, bl1, bl2, bl3;
            LDSM_X4(bh0, bh1, bh2, bh3, eHiB + off);
            LDSM_X4(bl0, bl1, bl2, bl3, eLoB + off);
            MMA16816(acc[0][0], afrag[0][0][ks][0], afrag[0][0][ks][1], afrag[0][0][ks][2], afrag[0][0][ks][3], bh0, bh1);
            MMA16816(acc[0][1], afrag[0][0][ks][0], afrag[0][0][ks][1], afrag[0][0][ks][2], afrag[0][0][ks][3], bh2, bh3);
            MMA16816(acc[1][0], afrag[0][1][ks][0], afrag[0][1][ks][1], afrag[0][1][ks][2], afrag[0][1][ks][3], bh0, bh1);
            MMA16816(acc[1][1], afrag[0][1][ks][0], afrag[0][1][ks][1], afrag[0][1][ks][2], afrag[0][1][ks][3], bh2, bh3);
            MMA16816(acc[0][0], afrag[0][0][ks][0], afrag[0][0][ks][1], afrag[0][0][ks][2], afrag[0][0][ks][3], bl0, bl1);
            MMA16816(acc[0][1], afrag[0][0][ks][0], afrag[0][0][ks][1], afrag[0][0][ks][2], afrag[0][0][ks][3], bl2, bl3);
            MMA16816(acc[1][0], afrag[0][1][ks][0], afrag[0][1][ks][1], afrag[0][1][ks][2], afrag[0][1][ks][3], bl0, bl1);
            MMA16816(acc[1][1], afrag[0][1][ks][0], afrag[0][1][ks][1], afrag[0][1][ks][2], afrag[0][1][ks][3], bl2, bl3);
            MMA16816(acc[0][0], afrag[1][0][ks][0], afrag[1][0][ks][1], afrag[1][0][ks][2], afrag[1][0][ks][3], bh0, bh1);
            MMA16816(acc[0][1], afrag[1][0][ks][0], afrag[1][0][ks][1], afrag[1][0][ks][2], afrag[1][0][ks][3], bh2, bh3);
            MMA16816(acc[1][0], afrag[1][1][ks][0], afrag[1][1][ks][1], afrag[1][1][ks][2], afrag[1][1][ks][3], bh0, bh1);
            MMA16816(acc[1][1], afrag[1][1][ks][0], afrag[1][1][ks][1], afrag[1][1][ks][2], afrag[1][1][ks][3], bh2, bh3);
        }

        int cb = ch*64 + cq*16 + (lane & 3)*2;
#pragma unroll
        for (int rt2 = 0; rt2 < 2; rt2++) {
#pragma unroll
            for (int ct = 0; ct < 2; ct++) {
                int c0 = cb + ct*8, c1 = c0 + 1;
                float e20 = sE2[c0], e21 = sE2[c1];
                float dA0 = fmaf(-2.f, acc[rt2][ct][0], e20);
                float dA1 = fmaf(-2.f, acc[rt2][ct][1], e21);
                float dB0 = fmaf(-2.f, acc[rt2][ct][2], e20);
                float dB1 = fmaf(-2.f, acc[rt2][ct][3], e21);
                float kA0 = __uint_as_float((__float_as_uint(dA0) & 0xFFFFFC00u) | (unsigned)c0);
                float kA1 = __uint_as_float((__float_as_uint(dA1) & 0xFFFFFC00u) | (unsigned)c1);
                float kB0 = __uint_as_float((__float_as_uint(dB0) & 0xFFFFFC00u) | (unsigned)c0);
                float kB1 = __uint_as_float((__float_as_uint(dB1) & 0xFFFFFC00u) | (unsigned)c1);
                float hi;
                hi = fmaxf(kk1[rt2][0], kA0); kk1[rt2][0] = fminf(kk1[rt2][0], kA0); kk2[rt2][0] = fminf(kk2[rt2][0], hi);
                hi = fmaxf(kk1[rt2][0], kA1); kk1[rt2][0] = fminf(kk1[rt2][0], kA1); kk2[rt2][0] = fminf(kk2[rt2][0], hi);
                hi = fmaxf(kk1[rt2][1], kB0); kk1[rt2][1] = fminf(kk1[rt2][1], kB0); kk2[rt2][1] = fminf(kk2[rt2][1], hi);
                hi = fmaxf(kk1[rt2][1], kB1); kk1[rt2][1] = fminf(kk1[rt2][1], kB1); kk2[rt2][1] = fminf(kk2[rt2][1], hi);
            }
        }

        if (ch + 1 < 16) CP_WAIT0();
        __syncthreads();
    }

    const unsigned FULL = 0xffffffffu;
#pragma unroll
    for (int off = 2; off > 0; off >>= 1) {
#pragma unroll
        for (int rt2 = 0; rt2 < 2; rt2++)
#pragma unroll
            for (int s = 0; s < 2; s++) {
                float o1 = __shfl_down_sync(FULL, kk1[rt2][s], off, 4);
                float o2 = __shfl_down_sync(FULL, kk2[rt2][s], off, 4);
                float hi = fmaxf(kk1[rt2][s], o1);
                kk1[rt2][s] = fminf(kk1[rt2][s], o1);
                kk2[rt2][s] = fminf(fminf(kk2[rt2][s], o2), hi);
            }
    }

    float* k1buf = (float*)(vsmem + VQ_B0H);
    float* k2buf = (float*)(vsmem + VQ_B0H + 1024);
    int* s_b1 = (int*)(vsmem + VQ_B0H + 2048);
    if ((lane & 3) == 0) {
        int g = lane >> 2;
#pragma unroll
        for (int rt2 = 0; rt2 < 2; rt2++) {
            int rA = rt*32 + rt2*16 + g;
            k1buf[rA*4 + cq]     = kk1[rt2][0];
            k2buf[rA*4 + cq]     = kk2[rt2][0];
            k1buf[(rA+8)*4 + cq] = kk1[rt2][1];
            k2buf[(rA+8)*4 + cq] = kk2[rt2][1];
        }
    }
    __syncthreads();

    const float* pool = (const float*)(vsmem + VQ_POOL);
    if (t < 64) {
        float m1 = INF;
#pragma unroll
        for (int q = 0; q < 4; q++) m1 = fminf(m1, k1buf[t*4 + q]);
        float m2 = INF;
#pragma unroll
        for (int q = 0; q < 4; q++) {
            float v1 = k1buf[t*4 + q], v2 = k2buf[t*4 + q];
            m2 = fminf(m2, (v1 > m1) ? v1 : INF);
            m2 = fminf(m2, (v2 > m1) ? v2 : INF);
        }
        int i1 = (int)(__float_as_uint(m1) & 1023u);
        int i2 = (int)(__float_as_uint(m2) & 1023u);
        int best = i1;
        if (i2 != i1) {
            const float4* frow = (const float4*)(pool + t*68);
            const float4* ea = (const float4*)(embed + (size_t)i1*64);
            const float4* eb = (const float4*)(embed + (size_t)i2*64);
            float da = 0.f, db = 0.f;
#pragma unroll
            for (int k = 0; k < 16; k++) {
                float4 f = frow[k], va = ea[k], vb = eb[k];
                da = fmaf(f.x, va.x, da); da = fmaf(f.y, va.y, da);
                da = fmaf(f.z, va.z, da); da = fmaf(f.w, va.w, da);
                db = fmaf(f.x, vb.x, db); db = fmaf(f.y, vb.y, db);
                db = fmaf(f.z, vb.z, db); db = fmaf(f.w, vb.w, db);
            }
            float dda = fmaf(-2.f, da, sE2[i1]);
            float ddb = fmaf(-2.f, db, sE2[i2]);
            if (better(ddb, i2, dda, i1)) best = i2;
        }
        s_b1[t] = best;
        g_idx[row0 + t] = best;
        out[YELEMS + row0 + t] = (float)best;
    }
    __syncthreads();

    float lacc = 0.f;
#pragma unroll
    for (int it = 0; it < 16; it++) {
        int e = it*256 + t;
        int r = e >> 6, d = e & 63;
        int ci = s_b1[r];
        float qv = embed[ci*64 + d];
        float fv = pool[r*68 + d];
        float df = qv - fv;
        lacc = fmaf(df, df, lacc);
    }

    float* s_red = (float*)(vsmem + VQ_B1H);
    s_red[t] = lacc;
    __syncthreads();
    for (int o = 128; o > 0; o >>= 1) {
        if (t < o) s_red[t] += s_red[t+o];
        __syncthreads();
    }
    if (t == 0) g_losspart[blockIdx.x] = s_red[0];
}

// ============================================================
// decoder: nearest-x2 upsample fused with conv2 (collapsed 2x2),
// quant gathered from embed via g_idx (L2-resident table)
// ============================================================
#define DCK 16
__global__ void __launch_bounds__(256) conv2up_k(const float* __restrict__ embed,
                                                 const float* __restrict__ bias)
{
    __shared__ float s_q[DCK][18][34];
    __shared__ float s_cw[48][DCK];
    __shared__ int s_ci[612];
    int t = threadIdx.x;
    int tx = t & 15, ty = t >> 4;
    int x0 = blockIdx.x*32, y0 = blockIdx.y*16, bb = blockIdx.z;

    for (int e = t; e < 612; e += 256) {
        int r = e / 34, c = e % 34;
        int qy = y0 - 1 + r, qx = x0 - 1 + c;
        int ci = -1;
        if (qy >= 0 && qy < 128 && qx >= 0 && qx < 128)
            ci = g_idx[(bb*128 + qy)*128 + qx];
        s_ci[e] = ci;
    }

    float acc[2][2][2][3];
#pragma unroll
    for (int a1 = 0; a1 < 2; a1++)
#pragma unroll
        for (int a2 = 0; a2 < 2; a2++)
#pragma unroll
            for (int a3 = 0; a3 < 2; a3++)
#pragma unroll
                for (int a4 = 0; a4 < 3; a4++) acc[a1][a2][a3][a4] = 0.f;

    for (int ch = 0; ch < 64/DCK; ch++) {
        __syncthreads();
        for (int e = t; e < 48*DCK; e += 256) {
            int row = e >> 4, dl = e & (DCK-1);
            s_cw[row][dl] = g_cw[row*64 + ch*DCK + dl];
        }
        for (int e = t; e < 612*DCK; e += 256) {
            int dl = e & (DCK-1);
            int cell = e >> 4;
            int ci = s_ci[cell];
            float v = (ci >= 0) ? embed[ci*64 + ch*DCK + dl] : 0.f;
            s_q[dl][cell / 34][cell % 34] = v;
        }
        __syncthreads();

#pragma unroll 4
        for (int dl = 0; dl < DCK; dl++) {
            float qv[3][4];
#pragma unroll
            for (int a = 0; a < 3; a++)
#pragma unroll
                for (int c = 0; c < 4; c++)
                    qv[a][c] = s_q[dl][ty + a][2*tx + c];
#pragma unroll
            for (int co = 0; co < 3; co++)
#pragma unroll
                for (int py = 0; py < 2; py++)
#pragma unroll
                    for (int px = 0; px < 2; px++) {
#pragma unroll
                        for (int ty_ = 0; ty_ < 2; ty_++)
#pragma unroll
                            for (int tx_ = 0; tx_ < 2; tx_++) {
                                float wv = s_cw[((py*2+px)*3+co)*4 + ty_*2+tx_][dl];
#pragma unroll
                                for (int xi = 0; xi < 2; xi++)
                                    acc[xi][py][px][co] =
                                        fmaf(qv[py+ty_][xi+px+tx_], wv, acc[xi][py][px][co]);
                            }
                    }
        }
    }

    int qy = y0 + ty;
#pragma unroll
    for (int co = 0; co < 3; co++) {
        float bv = bias[co];
#pragma unroll
        for (int xi = 0; xi < 2; xi++) {
            int qx = x0 + 2*tx + xi;
#pragma unroll
            for (int py = 0; py < 2; py++)
#pragma unroll
                for (int px = 0; px < 2; px++) {
                    int Y = 2*qy + py, X = 2*qx + px;
                    g_y2[((bb*3 + co) << 16) + (Y << 8) + X] = acc[xi][py][px][co] + bv;
                }
        }
    }
}

// ============================================================
// BN2 stats (float4)
// ============================================================
__global__ void __launch_bounds__(256) stats3_k()
{
    int c = blockIdx.x, s = blockIdx.y, t = threadIdx.x;
    const float4* src = (const float4*)g_y2;
    float sum = 0.f, sq = 0.f;
    int i0 = s * 4096;
    for (int i = i0 + t; i < i0 + 4096; i += 256) {
        int b = i >> 14, p4 = i & 16383;
        float4 v = src[((b*3 + c) << 14) + p4];
        sum += v.x + v.y + v.z + v.w;
        sq = fmaf(v.x, v.x, sq); sq = fmaf(v.y, v.y, sq);
        sq = fmaf(v.z, v.z, sq); sq = fmaf(v.w, v.w, sq);
    }
    __shared__ float ss[256], s2[256];
    ss[t] = sum; s2[t] = sq; __syncthreads();
    for (int o = 128; o > 0; o >>= 1) {
        if (t < o) { ss[t] += ss[t+o]; s2[t] += s2[t+o]; }
        __syncthreads();
    }
    if (t == 0) { g_part2[(c*32 + s)*2] = ss[0]; g_part2[(c*32 + s)*2 + 1] = s2[0]; }
}

// finalize BN2 + loss output (2048 loss partials)
__global__ void __launch_bounds__(256) fin2loss_k(const float* __restrict__ gamma,
                                                  const float* __restrict__ beta,
                                                  float* __restrict__ out)
{
    int t = threadIdx.x;
    if (t < 3) {
        float sum = 0.f, sq = 0.f;
        for (int s = 0; s < 32; s++) { sum += g_part2[(t*32+s)*2]; sq += g_part2[(t*32+s)*2+1]; }
        float inv = 1.f / (float)BNCNT;
        float mean = sum * inv;
        float var = sq * inv - mean*mean;
        float scale = gamma[t] * rsqrtf(var + EPSBN);
        g_bn2[t*2]   = scale;
        g_bn2[t*2+1] = beta[t] - mean*scale;
    }
    __shared__ float s[256];
    float acc = 0.f;
#pragma unroll
    for (int j = 0; j < 8; j++) acc += g_losspart[t + j*256];
    s[t] = acc;
    __syncthreads();
    for (int o = 128; o > 0; o >>= 1) {
        if (t < o) s[t] += s[t+o];
        __syncthreads();
    }
    if (t == 0) out[YELEMS + NPTS] = 0.25f * s[0] / (float)(NPTS * DD);
}

// ============================================================
// BN2 apply + tanh -> d_out (float4)
// ============================================================
__global__ void __launch_bounds__(256) bn2tanh_k(float* __restrict__ out)
{
    int e4 = blockIdx.x*256 + threadIdx.x;
    int c = (e4 >> 14) % 3;
    float sc = g_bn2[c*2], sh = g_bn2[c*2+1];
    float4 v = ((const float4*)g_y2)[e4];
    float4 r;
    r.x = tanhf(fmaf(v.x, sc, sh));
    r.y = tanhf(fmaf(v.y, sc, sh));
    r.z = tanhf(fmaf(v.z, sc, sh));
    r.w = tanhf(fmaf(v.w, sc, sh));
    ((float4*)out)[e4] = r;
}

// ============================================================
extern "C" void kernel_launch(void* const* d_in, const int* in_sizes, int n_in,
                              void* d_out, int out_size)
{
    const float* x   = (const float*)d_in[0];
    const float* w1  = (const float*)d_in[1];
    const float* b1  = (const float*)d_in[2];
    const float* g1  = (const float*)d_in[3];
    const float* be1 = (const float*)d_in[4];
    const float* em  = (const float*)d_in[5];
    const float* w2  = (const float*)d_in[6];
    const float* b2  = (const float*)d_in[7];
    const float* g2  = (const float*)d_in[8];
    const float* be2 = (const float*)d_in[9];
    float* out = (float*)d_out;
    (void)in_sizes; (void)n_in; (void)out_size;

    cudaFuncSetAttribute(conv1pool_k, cudaFuncAttributeMaxDynamicSharedMemorySize, C1_SMEM);
    cudaFuncSetAttribute(vq_k, cudaFuncAttributeMaxDynamicSharedMemorySize, VQ_SMEM_SZ);

    conv1pool_k<<<dim3(8,8,8), dim3(32,8), C1_SMEM>>>(x, w1, b1);   // 0
    finalize1_k<<<64, 256>>>(g1, be1);                              // 1
    prep2_k<<<140, 256>>>(em, w2);                                  // 2
    vq_k<<<NPTS/64, 256, VQ_SMEM_SZ>>>(em, out);                    // 3  <- profiled
    conv2up_k<<<dim3(4,8,8), 256>>>(em, b2);                        // 4
    stats3_k<<<dim3(3,32), 256>>>();                                // 5
    fin2loss_k<<<1, 256>>>(g2, be2, out);                           // 6
    bn2tanh_k<<<YELEMS/1024, 256>>>(out);                           // 7
}

// round 15
// speedup vs baseline: 1.0465x; 1.0052x over previous
#include <cuda_runtime.h>
#include <cuda_bf16.h>
#include <cstdint>
#include <math.h>

#define EPSBN 1e-5f

#define NB 8
#define CIN 3
#define HIMG 256
#define WIMG 256
#define DD 64
#define KC 1024
#define HP 128
#define WP 128
#define NPTS (NB*HP*WP)            /* 131072 */
#define YELEMS (NB*CIN*HIMG*WIMG)  /* 1572864 */
#define BNCNT (NB*HIMG*WIMG)       /* 524288 per channel */

// ---------------- scratch (device globals; allocation-free) ----------------
__device__ float g_praw[NPTS*DD];
__device__ __align__(16) __nv_bfloat16 g_ehi[KC*DD];
__device__ __align__(16) __nv_bfloat16 g_elo[KC*DD];
__device__ int   g_idx[NPTS];
__device__ float g_y2[YELEMS];
__device__ __align__(16) float g_e2[KC];
__device__ float g_cw[48*64];
__device__ float g_part1[64*512*2];
__device__ float g_part2[3*32*2];
__device__ float g_bn1[64*2];
__device__ float g_bn2[3*2];
__device__ float g_losspart[2048];

// ---------------- mma / async helpers ----------------
#define LDSM_X4(r0,r1,r2,r3,addr) \
    asm volatile("ldmatrix.sync.aligned.m8n8.x4.shared.b16 {%0,%1,%2,%3},[%4];" \
        : "=r"(r0),"=r"(r1),"=r"(r2),"=r"(r3) : "r"(addr))
#define MMA16816(c,a0,a1,a2,a3,b0,b1) \
    asm volatile("mma.sync.aligned.m16n8k16.row.col.f32.bf16.bf16.f32 " \
        "{%0,%1,%2,%3},{%4,%5,%6,%7},{%8,%9},{%0,%1,%2,%3};" \
        : "+f"((c)[0]),"+f"((c)[1]),"+f"((c)[2]),"+f"((c)[3]) \
        : "r"(a0),"r"(a1),"r"(a2),"r"(a3),"r"(b0),"r"(b1))
#define CP_ASYNC16(dst, src) \
    asm volatile("cp.async.ca.shared.global [%0], [%1], 16;" \
        :: "r"(dst), "l"(src) : "memory")
#define CP_COMMIT() asm volatile("cp.async.commit_group;" ::: "memory")
#define CP_WAIT0()  asm volatile("cp.async.wait_group 0;" ::: "memory")

__device__ __forceinline__ bool better(float da, int ia, float db, int ib) {
    return da < db || (da == db && ia < ib);
}

// ============================================================
// conv1 + bias + fused BN1 stats + fused maxpool2
// occ-3: half-size pool staging [16][16][33], co in 2 halves
// ============================================================
#define C1_SMEM (16*16*33*4)   /* 33792 */
__global__ void __launch_bounds__(256,3) conv1pool_k(const float* __restrict__ x,
                                                     const float* __restrict__ w,
                                                     const float* __restrict__ bias)
{
    __shared__ float s_in[3][34][34];
    __shared__ float s_w[64*27];
    __shared__ float s_b[64];
    __shared__ float s_sum[64*8];
    __shared__ float s_sq[64*8];
    extern __shared__ float s_pool[];   // [16][16][33]

    int tx = threadIdx.x, ty = threadIdx.y;
    int tid = ty*32 + tx;
    int wid = tid >> 5;
    int lane = tid & 31;
    int x0 = blockIdx.x*32, y0 = blockIdx.y*32, b = blockIdx.z;
    int bid = (b*8 + blockIdx.y)*8 + blockIdx.x;

    for (int i = tid; i < 64*27; i += 256) s_w[i] = w[i];
    if (tid < 64) s_b[tid] = bias[tid];
    for (int i = tid; i < 3*34*34; i += 256) {
        int c = i / (34*34); int r = i % (34*34);
        int yy = r / 34, xx = r % 34;
        int gy = y0 + yy - 1, gx = x0 + xx - 1;
        float v = 0.f;
        if (gy >= 0 && gy < 256 && gx >= 0 && gx < 256)
            v = x[((b*3 + c)*256 + gy)*256 + gx];
        s_in[c][yy][xx] = v;
    }
    __syncthreads();

    float rin[3][6][3];
#pragma unroll
    for (int c = 0; c < 3; c++)
#pragma unroll
        for (int r = 0; r < 6; r++)
#pragma unroll
            for (int q = 0; q < 3; q++)
                rin[c][r][q] = s_in[c][ty*4 + r][tx + q];

    const unsigned FULL = 0xffffffffu;
    int pxl = tx >> 1;
    int pr0 = ty*2;

    for (int h = 0; h < 2; h++) {
        if (h) __syncthreads();
        for (int co2 = 0; co2 < 32; co2++) {
            int co = h*32 + co2;
            float bb = s_b[co];
            float a0 = bb, a1 = bb, a2 = bb, a3 = bb;
#pragma unroll
            for (int c = 0; c < 3; c++)
#pragma unroll
                for (int ky = 0; ky < 3; ky++)
#pragma unroll
                    for (int kx = 0; kx < 3; kx++) {
                        float wv = s_w[co*27 + c*9 + ky*3 + kx];
                        a0 = fmaf(rin[c][0+ky][kx], wv, a0);
                        a1 = fmaf(rin[c][1+ky][kx], wv, a1);
                        a2 = fmaf(rin[c][2+ky][kx], wv, a2);
                        a3 = fmaf(rin[c][3+ky][kx], wv, a3);
                    }
            float s = a0 + a1 + a2 + a3;
            float q = a0*a0; q = fmaf(a1,a1,q); q = fmaf(a2,a2,q); q = fmaf(a3,a3,q);
#pragma unroll
            for (int o = 16; o > 0; o >>= 1) {
                s += __shfl_xor_sync(FULL, s, o);
                q += __shfl_xor_sync(FULL, q, o);
            }
            if (lane == 0) { s_sum[co*8 + wid] = s; s_sq[co*8 + wid] = q; }
            float m0 = fmaxf(a0, a1);
            float m1 = fmaxf(a2, a3);
            m0 = fmaxf(m0, __shfl_xor_sync(FULL, m0, 1));
            m1 = fmaxf(m1, __shfl_xor_sync(FULL, m1, 1));
            if ((tx & 1) == 0) {
                s_pool[(pr0*16 + pxl)*33 + co2]     = m0;
                s_pool[((pr0+1)*16 + pxl)*33 + co2] = m1;
            }
        }
        __syncthreads();

        int base = (((b*128 + (y0 >> 1))*128) + (x0 >> 1))*64 + h*32;
        for (int i = tid; i < 8192; i += 256) {
            int r = i >> 9, j = i & 511;
            int px = j >> 5, c = j & 31;
            g_praw[base + r*8192 + px*64 + c] = s_pool[(r*16 + px)*33 + c];
        }
    }

    if (tid < 64) {
        float S = 0.f, Q = 0.f;
#pragma unroll
        for (int i = 0; i < 8; i++) { S += s_sum[tid*8 + i]; Q += s_sq[tid*8 + i]; }
        g_part1[(tid*512 + bid)*2]     = S;
        g_part1[(tid*512 + bid)*2 + 1] = Q;
    }
}

// ============================================================
// combo: finalize BN1 (blocks 0-63) + embed prep (64-191) +
//        conv2 weight collapse (192-203). All independent.
// ============================================================
__global__ void __launch_bounds__(256) combo_k(const float* __restrict__ gamma,
                                               const float* __restrict__ beta,
                                               const float* __restrict__ embed,
                                               const float* __restrict__ w2)
{
    int bb = blockIdx.x;
    int t = threadIdx.x;
    if (bb < 64) {
        int c = bb;
        float s = 0.f, q = 0.f;
        for (int i = t; i < 512; i += 256) {
            s += g_part1[(c*512 + i)*2];
            q += g_part1[(c*512 + i)*2 + 1];
        }
        __shared__ float ss[256], s2[256];
        ss[t] = s; s2[t] = q; __syncthreads();
        for (int o = 128; o > 0; o >>= 1) {
            if (t < o) { ss[t] += ss[t+o]; s2[t] += s2[t+o]; }
            __syncthreads();
        }
        if (t == 0) {
            float inv = 1.f / (float)BNCNT;
            float mean = ss[0] * inv;
            float var = s2[0] * inv - mean*mean;
            float scale = gamma[c] * rsqrtf(var + EPSBN);
            g_bn1[c*2]   = scale;
            g_bn1[c*2+1] = beta[c] - mean*scale;
        }
    } else if (bb < 192) {
        int code = (bb - 64)*8 + (t >> 5);
        int lane = t & 31;
        float a = embed[code*64 + lane];
        float b2v = embed[code*64 + 32 + lane];
        __nv_bfloat16 ah = __float2bfloat16(a);
        __nv_bfloat16 bh = __float2bfloat16(b2v);
        g_ehi[code*64 + lane] = ah;
        g_ehi[code*64 + 32 + lane] = bh;
        g_elo[code*64 + lane] = __float2bfloat16(a - __bfloat162float(ah));
        g_elo[code*64 + 32 + lane] = __float2bfloat16(b2v - __bfloat162float(bh));
        float s = a*a + b2v*b2v;
#pragma unroll
        for (int o = 16; o > 0; o >>= 1)
            s += __shfl_down_sync(0xffffffffu, s, o);
        if (lane == 0) g_e2[code] = s;
    } else {
        int e = (bb - 192)*256 + t;
        if (e < 48*64) {
            int d = e & 63;
            int rest = e >> 6;
            int tap = rest & 3;
            int tx_ = tap & 1, ty_ = tap >> 1;
            int co = (rest >> 2) % 3;
            int ph = rest / 12;
            int px = ph & 1, py = ph >> 1;
            float s = 0.f;
            for (int ky = 0; ky < 3; ky++) {
                int mapy = (py == 0) ? ((ky == 0) ? 0 : 1) : ((ky < 2) ? 0 : 1);
                if (mapy != ty_) continue;
                for (int kx = 0; kx < 3; kx++) {
                    int mapx = (px == 0) ? ((kx == 0) ? 0 : 1) : ((kx < 2) ? 0 : 1);
                    if (mapx != tx_) continue;
                    s += w2[((co*64 + d)*3 + ky)*3 + kx];
                }
            }
            g_cw[e] = s;
        }
    }
}

// ============================================================
// VQ: fused BN+ReLU+bf16-split of A (from g_praw) + hi/lo 3-GEMM
// via mma.sync with cp.async double-buffered B (1 sync/chunk).
// Packed-key top-2 + exact fp32 refine. Writes indices only.
// ============================================================
#define VQ_AHI  0
#define VQ_ALO  8192
#define VQ_POOL 16384
#define VQ_B0H  33792
#define VQ_B0L  41984
#define VQ_B1H  50176
#define VQ_B1L  58368
#define VQ_E2   66560
#define VQ_SMEM_SZ 70656

__global__ void __launch_bounds__(256,2) vq_k(const float* __restrict__ embed,
                                              float* __restrict__ out)
{
    extern __shared__ __align__(16) char vsmem[];
    __shared__ float s_ss[128];
    int t = threadIdx.x;
    int w = t >> 5, lane = t & 31;
    int rt = w & 1;
    int cq = w >> 1;
    int row0 = blockIdx.x * 64;
    unsigned int uBase = (unsigned int)__cvta_generic_to_shared(vsmem);
    const char* ehp = (const char*)g_ehi;
    const char* elp = (const char*)g_elo;

    if (t < 128) s_ss[t] = g_bn1[t];

    {
        unsigned int bh = uBase + VQ_B0H;
        unsigned int bl = uBase + VQ_B0L;
#pragma unroll
        for (int j = 0; j < 4; j++) {
            int idx = t + j*256;
            int e = idx & 511;
            int r = e >> 3, kc = e & 7;
            unsigned int doff = (unsigned int)((r*8 + (kc ^ (r & 7))) << 4);
            if (idx < 512) CP_ASYNC16(bh + doff, ehp + e*16);
            else           CP_ASYNC16(bl + doff, elp + e*16);
        }
        CP_COMMIT();
    }
    ((float4*)(vsmem + VQ_E2))[t] = ((const float4*)g_e2)[t];
    __syncthreads();

    {
        float* pool = (float*)(vsmem + VQ_POOL);
        uint4* ah4 = (uint4*)(vsmem + VQ_AHI);
        uint4* al4 = (uint4*)(vsmem + VQ_ALO);
#pragma unroll
        for (int j = 0; j < 2; j++) {
            int e8 = t + j*256;
            int r = e8 >> 3, c8 = e8 & 7;
            int k0 = c8*8;
            const float4* pr = (const float4*)(g_praw + (size_t)(row0 + r)*64 + k0);
            float4 v0 = pr[0], v1 = pr[1];
            float vv[8] = {v0.x, v0.y, v0.z, v0.w, v1.x, v1.y, v1.z, v1.w};
            unsigned hh[8], ll[8];
#pragma unroll
            for (int i = 0; i < 8; i++) {
                float vb = fmaxf(fmaf(vv[i], s_ss[(k0+i)*2], s_ss[(k0+i)*2+1]), 0.f);
                vv[i] = vb;
                __nv_bfloat16 hb = __float2bfloat16(vb);
                hh[i] = __bfloat16_as_ushort(hb);
                ll[i] = __bfloat16_as_ushort(__float2bfloat16(vb - __bfloat162float(hb)));
            }
            float* pp = pool + r*68 + k0;
            ((float4*)pp)[0] = make_float4(vv[0], vv[1], vv[2], vv[3]);
            ((float4*)pp)[1] = make_float4(vv[4], vv[5], vv[6], vv[7]);
            int dst = r*8 + (c8 ^ (r & 7));
            uint4 H, L;
            H.x = (hh[1]<<16)|hh[0]; H.y = (hh[3]<<16)|hh[2];
            H.z = (hh[5]<<16)|hh[4]; H.w = (hh[7]<<16)|hh[6];
            L.x = (ll[1]<<16)|ll[0]; L.y = (ll[3]<<16)|ll[2];
            L.z = (ll[5]<<16)|ll[4]; L.w = (ll[7]<<16)|ll[6];
            ah4[dst] = H;
            al4[dst] = L;
        }
    }
    CP_WAIT0();
    __syncthreads();

    unsigned int afrag[2][2][4][4];
    {
        unsigned int aHiB = uBase + VQ_AHI;
        unsigned int aLoB = uBase + VQ_ALO;
        int ahalf = lane >> 4;
#pragma unroll
        for (int rt2 = 0; rt2 < 2; rt2++) {
            int ar = rt*32 + rt2*16 + (lane & 15);
#pragma unroll
            for (int ks = 0; ks < 4; ks++) {
                unsigned int off = (unsigned int)(ar*128 + (((ks*2 + ahalf) ^ (ar & 7)) << 4));
                LDSM_X4(afrag[0][rt2][ks][0], afrag[0][rt2][ks][1], afrag[0][rt2][ks][2], afrag[0][rt2][ks][3], aHiB + off);
                LDSM_X4(afrag[1][rt2][ks][0], afrag[1][rt2][ks][1], afrag[1][rt2][ks][2], afrag[1][rt2][ks][3], aLoB + off);
            }
        }
    }

    const float* sE2 = (const float*)(vsmem + VQ_E2);
    const float INF = __int_as_float(0x7f800000);
    float kk1[2][2], kk2[2][2];
#pragma unroll
    for (int i = 0; i < 2; i++)
#pragma unroll
        for (int j = 0; j < 2; j++) { kk1[i][j] = INF; kk2[i][j] = INF; }

    int brow = cq*16 + (lane >> 4)*8 + (lane & 7);
    int bkhalf = (lane >> 3) & 1;

    for (int ch = 0; ch < 16; ch++) {
        int cur = ch & 1;
        if (ch + 1 < 16) {
            unsigned int bh = uBase + (cur ? VQ_B0H : VQ_B1H);
            unsigned int bl = uBase + (cur ? VQ_B0L : VQ_B1L);
            const char* sh = ehp + (ch+1)*8192;
            const char* sl = elp + (ch+1)*8192;
#pragma unroll
            for (int j = 0; j < 4; j++) {
                int idx = t + j*256;
                int e = idx & 511;
                int r = e >> 3, kc = e & 7;
                unsigned int doff = (unsigned int)((r*8 + (kc ^ (r & 7))) << 4);
                if (idx < 512) CP_ASYNC16(bh + doff, sh + e*16);
                else           CP_ASYNC16(bl + doff, sl + e*16);
            }
            CP_COMMIT();
        }

        unsigned int eHiB = uBase + (cur ? VQ_B1H : VQ_B0H);
        unsigned int eLoB = uBase + (cur ? VQ_B1L : VQ_B0L);

        float acc[2][2][4];
#pragma unroll
        for (int i = 0; i < 2; i++)
#pragma unroll
            for (int j = 0; j < 2; j++)
#pragma unroll
                for (int q = 0; q < 4; q++) acc[i][j][q] = 0.f;

#pragma unroll
        for (int ks = 0; ks < 4; ks++) {
            int kc = ks*2 + bkhalf;
            unsigned int off = (unsigned int)(brow*128 + ((kc ^ (brow & 7)) << 4));
            unsigned int bh0, bh1, bh2, bh3, bl0, bl1, bl2, bl3;
            LDSM_X4(bh0, bh1, bh2, bh3, eHiB + off);
            LDSM_X4(bl0, bl1, bl2, bl3, eLoB + off);
            MMA16816(acc[0][0], afrag[0][0][ks][0], afrag[0][0][ks][1], afrag[0][0][ks][2], afrag[0][0][ks][3], bh0, bh1);
            MMA16816(acc[0][1], afrag[0][0][ks][0], afrag[0][0][ks][1], afrag[0][0][ks][2], afrag[0][0][ks][3], bh2, bh3);
            MMA16816(acc[1][0], afrag[0][1][ks][0], afrag[0][1][ks][1], afrag[0][1][ks][2], afrag[0][1][ks][3], bh0, bh1);
            MMA16816(acc[1][1], afrag[0][1][ks][0], afrag[0][1][ks][1], afrag[0][1][ks][2], afrag[0][1][ks][3], bh2, bh3);
            MMA16816(acc[0][0], afrag[0][0][ks][0], afrag[0][0][ks][1], afrag[0][0][ks][2], afrag[0][0][ks][3], bl0, bl1);
            MMA16816(acc[0][1], afrag[0][0][ks][0], afrag[0][0][ks][1], afrag[0][0][ks][2], afrag[0][0][ks][3], bl2, bl3);
            MMA16816(acc[1][0], afrag[0][1][ks][0], afrag[0][1][ks][1], afrag[0][1][ks][2], afrag[0][1][ks][3], bl0, bl1);
            MMA16816(acc[1][1], afrag[0][1][ks][0], afrag[0][1][ks][1], afrag[0][1][ks][2], afrag[0][1][ks][3], bl2, bl3);
            MMA16816(acc[0][0], afrag[1][0][ks][0], afrag[1][0][ks][1], afrag[1][0][ks][2], afrag[1][0][ks][3], bh0, bh1);
            MMA16816(acc[0][1], afrag[1][0][ks][0], afrag[1][0][ks][1], afrag[1][0][ks][2], afrag[1][0][ks][3], bh2, bh3);
            MMA16816(acc[1][0], afrag[1][1][ks][0], afrag[1][1][ks][1], afrag[1][1][ks][2], afrag[1][1][ks][3], bh0, bh1);
            MMA16816(acc[1][1], afrag[1][1][ks][0], afrag[1][1][ks][1], afrag[1][1][ks][2], afrag[1][1][ks][3], bh2, bh3);
        }

        int cb = ch*64 + cq*16 + (lane & 3)*2;
#pragma unroll
        for (int rt2 = 0; rt2 < 2; rt2++) {
#pragma unroll
            for (int ct = 0; ct < 2; ct++) {
                int c0 = cb + ct*8, c1 = c0 + 1;
                float e20 = sE2[c0], e21 = sE2[c1];
                float dA0 = fmaf(-2.f, acc[rt2][ct][0], e20);
                float dA1 = fmaf(-2.f, acc[rt2][ct][1], e21);
                float dB0 = fmaf(-2.f, acc[rt2][ct][2], e20);
                float dB1 = fmaf(-2.f, acc[rt2][ct][3], e21);
                float kA0 = __uint_as_float((__float_as_uint(dA0) & 0xFFFFFC00u) | (unsigned)c0);
                float kA1 = __uint_as_float((__float_as_uint(dA1) & 0xFFFFFC00u) | (unsigned)c1);
                float kB0 = __uint_as_float((__float_as_uint(dB0) & 0xFFFFFC00u) | (unsigned)c0);
                float kB1 = __uint_as_float((__float_as_uint(dB1) & 0xFFFFFC00u) | (unsigned)c1);
                float hi;
                hi = fmaxf(kk1[rt2][0], kA0); kk1[rt2][0] = fminf(kk1[rt2][0], kA0); kk2[rt2][0] = fminf(kk2[rt2][0], hi);
                hi = fmaxf(kk1[rt2][0], kA1); kk1[rt2][0] = fminf(kk1[rt2][0], kA1); kk2[rt2][0] = fminf(kk2[rt2][0], hi);
                hi = fmaxf(kk1[rt2][1], kB0); kk1[rt2][1] = fminf(kk1[rt2][1], kB0); kk2[rt2][1] = fminf(kk2[rt2][1], hi);
                hi = fmaxf(kk1[rt2][1], kB1); kk1[rt2][1] = fminf(kk1[rt2][1], kB1); kk2[rt2][1] = fminf(kk2[rt2][1], hi);
            }
        }

        if (ch + 1 < 16) CP_WAIT0();
        __syncthreads();
    }

    const unsigned FULL = 0xffffffffu;
#pragma unroll
    for (int off = 2; off > 0; off >>= 1) {
#pragma unroll
        for (int rt2 = 0; rt2 < 2; rt2++)
#pragma unroll
            for (int s = 0; s < 2; s++) {
                float o1 = __shfl_down_sync(FULL, kk1[rt2][s], off, 4);
                float o2 = __shfl_down_sync(FULL, kk2[rt2][s], off, 4);
                float hi = fmaxf(kk1[rt2][s], o1);
                kk1[rt2][s] = fminf(kk1[rt2][s], o1);
                kk2[rt2][s] = fminf(fminf(kk2[rt2][s], o2), hi);
            }
    }

    float* k1buf = (float*)(vsmem + VQ_B0H);
    float* k2buf = (float*)(vsmem + VQ_B0H + 1024);
    int* s_b1 = (int*)(vsmem + VQ_B0H + 2048);
    if ((lane & 3) == 0) {
        int g = lane >> 2;
#pragma unroll
        for (int rt2 = 0; rt2 < 2; rt2++) {
            int rA = rt*32 + rt2*16 + g;
            k1buf[rA*4 + cq]     = kk1[rt2][0];
            k2buf[rA*4 + cq]     = kk2[rt2][0];
            k1buf[(rA+8)*4 + cq] = kk1[rt2][1];
            k2buf[(rA+8)*4 + cq] = kk2[rt2][1];
        }
    }
    __syncthreads();

    const float* pool = (const float*)(vsmem + VQ_POOL);
    if (t < 64) {
        float m1 = INF;
#pragma unroll
        for (int q = 0; q < 4; q++) m1 = fminf(m1, k1buf[t*4 + q]);
        float m2 = INF;
#pragma unroll
        for (int q = 0; q < 4; q++) {
            float v1 = k1buf[t*4 + q], v2 = k2buf[t*4 + q];
            m2 = fminf(m2, (v1 > m1) ? v1 : INF);
            m2 = fminf(m2, (v2 > m1) ? v2 : INF);
        }
        int i1 = (int)(__float_as_uint(m1) & 1023u);
        int i2 = (int)(__float_as_uint(m2) & 1023u);
        int best = i1;
        if (i2 != i1) {
            const float4* frow = (const float4*)(pool + t*68);
            const float4* ea = (const float4*)(embed + (size_t)i1*64);
            const float4* eb = (const float4*)(embed + (size_t)i2*64);
            float da = 0.f, db = 0.f;
#pragma unroll
            for (int k = 0; k < 16; k++) {
                float4 f = frow[k], va = ea[k], vb = eb[k];
                da = fmaf(f.x, va.x, da); da = fmaf(f.y, va.y, da);
                da = fmaf(f.z, va.z, da); da = fmaf(f.w, va.w, da);
                db = fmaf(f.x, vb.x, db); db = fmaf(f.y, vb.y, db);
                db = fmaf(f.z, vb.z, db); db = fmaf(f.w, vb.w, db);
            }
            float dda = fmaf(-2.f, da, sE2[i1]);
            float ddb = fmaf(-2.f, db, sE2[i2]);
            if (better(ddb, i2, dda, i1)) best = i2;
        }
        s_b1[t] = best;
        g_idx[row0 + t] = best;
        out[YELEMS + row0 + t] = (float)best;
    }
    __syncthreads();

    float lacc = 0.f;
#pragma unroll
    for (int it = 0; it < 16; it++) {
        int e = it*256 + t;
        int r = e >> 6, d = e & 63;
        int ci = s_b1[r];
        float qv = embed[ci*64 + d];
        float fv = pool[r*68 + d];
        float df = qv - fv;
        lacc = fmaf(df, df, lacc);
    }

    float* s_red = (float*)(vsmem + VQ_B1H);
    s_red[t] = lacc;
    __syncthreads();
    for (int o = 128; o > 0; o >>= 1) {
        if (t < o) s_red[t] += s_red[t+o];
        __syncthreads();
    }
    if (t == 0) g_losspart[blockIdx.x] = s_red[0];
}

// ============================================================
// decoder: nearest-x2 upsample fused with conv2 (collapsed 2x2),
// quant gathered from embed via g_idx (L2-resident table)
// ============================================================
#define DCK 16
__global__ void __launch_bounds__(256) conv2up_k(const float* __restrict__ embed,
                                                 const float* __restrict__ bias)
{
    __shared__ float s_q[DCK][18][34];
    __shared__ float s_cw[48][DCK];
    __shared__ int s_ci[612];
    int t = threadIdx.x;
    int tx = t & 15, ty = t >> 4;
    int x0 = blockIdx.x*32, y0 = blockIdx.y*16, bb = blockIdx.z;

    for (int e = t; e < 612; e += 256) {
        int r = e / 34, c = e % 34;
        int qy = y0 - 1 + r, qx = x0 - 1 + c;
        int ci = -1;
        if (qy >= 0 && qy < 128 && qx >= 0 && qx < 128)
            ci = g_idx[(bb*128 + qy)*128 + qx];
        s_ci[e] = ci;
    }

    float acc[2][2][2][3];
#pragma unroll
    for (int a1 = 0; a1 < 2; a1++)
#pragma unroll
        for (int a2 = 0; a2 < 2; a2++)
#pragma unroll
            for (int a3 = 0; a3 < 2; a3++)
#pragma unroll
                for (int a4 = 0; a4 < 3; a4++) acc[a1][a2][a3][a4] = 0.f;

    for (int ch = 0; ch < 64/DCK; ch++) {
        __syncthreads();
        for (int e = t; e < 48*DCK; e += 256) {
            int row = e >> 4, dl = e & (DCK-1);
            s_cw[row][dl] = g_cw[row*64 + ch*DCK + dl];
        }
        for (int e = t; e < 612*DCK; e += 256) {
            int dl = e & (DCK-1);
            int cell = e >> 4;
            int ci = s_ci[cell];
            float v = (ci >= 0) ? embed[ci*64 + ch*DCK + dl] : 0.f;
            s_q[dl][cell / 34][cell % 34] = v;
        }
        __syncthreads();

#pragma unroll 4
        for (int dl = 0; dl < DCK; dl++) {
            float qv[3][4];
#pragma unroll
            for (int a = 0; a < 3; a++)
#pragma unroll
                for (int c = 0; c < 4; c++)
                    qv[a][c] = s_q[dl][ty + a][2*tx + c];
#pragma unroll
            for (int co = 0; co < 3; co++)
#pragma unroll
                for (int py = 0; py < 2; py++)
#pragma unroll
                    for (int px = 0; px < 2; px++) {
#pragma unroll
                        for (int ty_ = 0; ty_ < 2; ty_++)
#pragma unroll
                            for (int tx_ = 0; tx_ < 2; tx_++) {
                                float wv = s_cw[((py*2+px)*3+co)*4 + ty_*2+tx_][dl];
#pragma unroll
                                for (int xi = 0; xi < 2; xi++)
                                    acc[xi][py][px][co] =
                                        fmaf(qv[py+ty_][xi+px+tx_], wv, acc[xi][py][px][co]);
                            }
                    }
        }
    }

    int qy = y0 + ty;
#pragma unroll
    for (int co = 0; co < 3; co++) {
        float bv = bias[co];
#pragma unroll
        for (int xi = 0; xi < 2; xi++) {
            int qx = x0 + 2*tx + xi;
#pragma unroll
            for (int py = 0; py < 2; py++)
#pragma unroll
                for (int px = 0; px < 2; px++) {
                    int Y = 2*qy + py, X = 2*qx + px;
                    g_y2[((bb*3 + co) << 16) + (Y << 8) + X] = acc[xi][py][px][co] + bv;
                }
        }
    }
}

// ============================================================
// BN2 stats (float4)
// ============================================================
__global__ void __launch_bounds__(256) stats3_k()
{
    int c = blockIdx.x, s = blockIdx.y, t = threadIdx.x;
    const float4* src = (const float4*)g_y2;
    float sum = 0.f, sq = 0.f;
    int i0 = s * 4096;
    for (int i = i0 + t; i < i0 + 4096; i += 256) {
        int b = i >> 14, p4 = i & 16383;
        float4 v = src[((b*3 + c) << 14) + p4];
        sum += v.x + v.y + v.z + v.w;
        sq = fmaf(v.x, v.x, sq); sq = fmaf(v.y, v.y, sq);
        sq = fmaf(v.z, v.z, sq); sq = fmaf(v.w, v.w, sq);
    }
    __shared__ float ss[256], s2[256];
    ss[t] = sum; s2[t] = sq; __syncthreads();
    for (int o = 128; o > 0; o >>= 1) {
        if (t < o) { ss[t] += ss[t+o]; s2[t] += s2[t+o]; }
        __syncthreads();
    }
    if (t == 0) { g_part2[(c*32 + s)*2] = ss[0]; g_part2[(c*32 + s)*2 + 1] = s2[0]; }
}

// finalize BN2 + loss output (2048 loss partials)
__global__ void __launch_bounds__(256) fin2loss_k(const float* __restrict__ gamma,
                                                  const float* __restrict__ beta,
                                                  float* __restrict__ out)
{
    int t = threadIdx.x;
    if (t < 3) {
        float sum = 0.f, sq = 0.f;
        for (int s = 0; s < 32; s++) { sum += g_part2[(t*32+s)*2]; sq += g_part2[(t*32+s)*2+1]; }
        float inv = 1.f / (float)BNCNT;
        float mean = sum * inv;
        float var = sq * inv - mean*mean;
        float scale = gamma[t] * rsqrtf(var + EPSBN);
        g_bn2[t*2]   = scale;
        g_bn2[t*2+1] = beta[t] - mean*scale;
    }
    __shared__ float s[256];
    float acc = 0.f;
#pragma unroll
    for (int j = 0; j < 8; j++) acc += g_losspart[t + j*256];
    s[t] = acc;
    __syncthreads();
    for (int o = 128; o > 0; o >>= 1) {
        if (t < o) s[t] += s[t+o];
        __syncthreads();
    }
    if (t == 0) out[YELEMS + NPTS] = 0.25f * s[0] / (float)(NPTS * DD);
}

// ============================================================
// BN2 apply + tanh -> d_out (float4)
// ============================================================
__global__ void __launch_bounds__(256) bn2tanh_k(float* __restrict__ out)
{
    int e4 = blockIdx.x*256 + threadIdx.x;
    int c = (e4 >> 14) % 3;
    float sc = g_bn2[c*2], sh = g_bn2[c*2+1];
    float4 v = ((const float4*)g_y2)[e4];
    float4 r;
    r.x = tanhf(fmaf(v.x, sc, sh));
    r.y = tanhf(fmaf(v.y, sc, sh));
    r.z = tanhf(fmaf(v.z, sc, sh));
    r.w = tanhf(fmaf(v.w, sc, sh));
    ((float4*)out)[e4] = r;
}

// ============================================================
extern "C" void kernel_launch(void* const* d_in, const int* in_sizes, int n_in,
                              void* d_out, int out_size)
{
    const float* x   = (const float*)d_in[0];
    const float* w1  = (const float*)d_in[1];
    const float* b1  = (const float*)d_in[2];
    const float* g1  = (const float*)d_in[3];
    const float* be1 = (const float*)d_in[4];
    const float* em  = (const float*)d_in[5];
    const float* w2  = (const float*)d_in[6];
    const float* b2  = (const float*)d_in[7];
    const float* g2  = (const float*)d_in[8];
    const float* be2 = (const float*)d_in[9];
    float* out = (float*)d_out;
    (void)in_sizes; (void)n_in; (void)out_size;

    cudaFuncSetAttribute(conv1pool_k, cudaFuncAttributeMaxDynamicSharedMemorySize, C1_SMEM);
    cudaFuncSetAttribute(vq_k, cudaFuncAttributeMaxDynamicSharedMemorySize, VQ_SMEM_SZ);

    conv1pool_k<<<dim3(8,8,8), dim3(32,8), C1_SMEM>>>(x, w1, b1);   // 0
    combo_k<<<204, 256>>>(g1, be1, em, w2);                         // 1
    vq_k<<<NPTS/64, 256, VQ_SMEM_SZ>>>(em, out);                    // 2
    conv2up_k<<<dim3(4,8,8), 256>>>(em, b2);                        // 3
    stats3_k<<<dim3(3,32), 256>>>();                                // 4
    fin2loss_k<<<1, 256>>>(g2, be2, out);                           // 5
    bn2tanh_k<<<YELEMS/1024, 256>>>(out);                           // 6
}

// round 16
// speedup vs baseline: 1.1124x; 1.0629x over previous
#include <cuda_runtime.h>
#include <cuda_bf16.h>
#include <cstdint>
#include <math.h>

#define EPSBN 1e-5f

#define NB 8
#define CIN 3
#define HIMG 256
#define WIMG 256
#define DD 64
#define KC 1024
#define HP 128
#define WP 128
#define NPTS (NB*HP*WP)            /* 131072 */
#define YELEMS (NB*CIN*HIMG*WIMG)  /* 1572864 */
#define BNCNT (NB*HIMG*WIMG)       /* 524288 per channel */

// ---------------- scratch (device globals; allocation-free) ----------------
__device__ float g_praw[NPTS*DD];
__device__ __align__(16) __nv_bfloat16 g_ehi[KC*DD];
__device__ __align__(16) __nv_bfloat16 g_elo[KC*DD];
__device__ int   g_idx[NPTS];
__device__ float g_y2[YELEMS];
__device__ __align__(16) float g_e2[KC];
__device__ float g_cw[48*64];
__device__ float g_part1[64*512*2];
__device__ float g_part2[3*32*2];
__device__ float g_bn1[64*2];
__device__ float g_bn2[3*2];
__device__ float g_losspart[2048];

// ---------------- mma / async helpers ----------------
#define LDSM_X4(r0,r1,r2,r3,addr) \
    asm volatile("ldmatrix.sync.aligned.m8n8.x4.shared.b16 {%0,%1,%2,%3},[%4];" \
        : "=r"(r0),"=r"(r1),"=r"(r2),"=r"(r3) : "r"(addr))
#define MMA16816(c,a0,a1,a2,a3,b0,b1) \
    asm volatile("mma.sync.aligned.m16n8k16.row.col.f32.bf16.bf16.f32 " \
        "{%0,%1,%2,%3},{%4,%5,%6,%7},{%8,%9},{%0,%1,%2,%3};" \
        : "+f"((c)[0]),"+f"((c)[1]),"+f"((c)[2]),"+f"((c)[3]) \
        : "r"(a0),"r"(a1),"r"(a2),"r"(a3),"r"(b0),"r"(b1))
#define CP_ASYNC16(dst, src) \
    asm volatile("cp.async.ca.shared.global [%0], [%1], 16;" \
        :: "r"(dst), "l"(src) : "memory")
#define CP_COMMIT() asm volatile("cp.async.commit_group;" ::: "memory")
#define CP_WAIT0()  asm volatile("cp.async.wait_group 0;" ::: "memory")

__device__ __forceinline__ bool better(float da, int ia, float db, int ib) {
    return da < db || (da == db && ia < ib);
}

// ============================================================
// conv1 + bias + fused BN1 stats + fused maxpool2
// occ-3: half-size pool staging [16][16][33], co in 2 halves
// ============================================================
#define C1_SMEM (16*16*33*4)   /* 33792 */
__global__ void __launch_bounds__(256,3) conv1pool_k(const float* __restrict__ x,
                                                     const float* __restrict__ w,
                                                     const float* __restrict__ bias)
{
    __shared__ float s_in[3][34][34];
    __shared__ float s_w[64*27];
    __shared__ float s_b[64];
    __shared__ float s_sum[64*8];
    __shared__ float s_sq[64*8];
    extern __shared__ float s_pool[];   // [16][16][33]

    int tx = threadIdx.x, ty = threadIdx.y;
    int tid = ty*32 + tx;
    int wid = tid >> 5;
    int lane = tid & 31;
    int x0 = blockIdx.x*32, y0 = blockIdx.y*32, b = blockIdx.z;
    int bid = (b*8 + blockIdx.y)*8 + blockIdx.x;

    for (int i = tid; i < 64*27; i += 256) s_w[i] = w[i];
    if (tid < 64) s_b[tid] = bias[tid];
    for (int i = tid; i < 3*34*34; i += 256) {
        int c = i / (34*34); int r = i % (34*34);
        int yy = r / 34, xx = r % 34;
        int gy = y0 + yy - 1, gx = x0 + xx - 1;
        float v = 0.f;
        if (gy >= 0 && gy < 256 && gx >= 0 && gx < 256)
            v = x[((b*3 + c)*256 + gy)*256 + gx];
        s_in[c][yy][xx] = v;
    }
    __syncthreads();

    float rin[3][6][3];
#pragma unroll
    for (int c = 0; c < 3; c++)
#pragma unroll
        for (int r = 0; r < 6; r++)
#pragma unroll
            for (int q = 0; q < 3; q++)
                rin[c][r][q] = s_in[c][ty*4 + r][tx + q];

    const unsigned FULL = 0xffffffffu;
    int pxl = tx >> 1;
    int pr0 = ty*2;

    for (int h = 0; h < 2; h++) {
        if (h) __syncthreads();
        for (int co2 = 0; co2 < 32; co2++) {
            int co = h*32 + co2;
            float bb = s_b[co];
            float a0 = bb, a1 = bb, a2 = bb, a3 = bb;
#pragma unroll
            for (int c = 0; c < 3; c++)
#pragma unroll
                for (int ky = 0; ky < 3; ky++)
#pragma unroll
                    for (int kx = 0; kx < 3; kx++) {
                        float wv = s_w[co*27 + c*9 + ky*3 + kx];
                        a0 = fmaf(rin[c][0+ky][kx], wv, a0);
                        a1 = fmaf(rin[c][1+ky][kx], wv, a1);
                        a2 = fmaf(rin[c][2+ky][kx], wv, a2);
                        a3 = fmaf(rin[c][3+ky][kx], wv, a3);
                    }
            float s = a0 + a1 + a2 + a3;
            float q = a0*a0; q = fmaf(a1,a1,q); q = fmaf(a2,a2,q); q = fmaf(a3,a3,q);
#pragma unroll
            for (int o = 16; o > 0; o >>= 1) {
                s += __shfl_xor_sync(FULL, s, o);
                q += __shfl_xor_sync(FULL, q, o);
            }
            if (lane == 0) { s_sum[co*8 + wid] = s; s_sq[co*8 + wid] = q; }
            float m0 = fmaxf(a0, a1);
            float m1 = fmaxf(a2, a3);
            m0 = fmaxf(m0, __shfl_xor_sync(FULL, m0, 1));
            m1 = fmaxf(m1, __shfl_xor_sync(FULL, m1, 1));
            if ((tx & 1) == 0) {
                s_pool[(pr0*16 + pxl)*33 + co2]     = m0;
                s_pool[((pr0+1)*16 + pxl)*33 + co2] = m1;
            }
        }
        __syncthreads();

        int base = (((b*128 + (y0 >> 1))*128) + (x0 >> 1))*64 + h*32;
        for (int i = tid; i < 8192; i += 256) {
            int r = i >> 9, j = i & 511;
            int px = j >> 5, c = j & 31;
            g_praw[base + r*8192 + px*64 + c] = s_pool[(r*16 + px)*33 + c];
        }
    }

    if (tid < 64) {
        float S = 0.f, Q = 0.f;
#pragma unroll
        for (int i = 0; i < 8; i++) { S += s_sum[tid*8 + i]; Q += s_sq[tid*8 + i]; }
        g_part1[(tid*512 + bid)*2]     = S;
        g_part1[(tid*512 + bid)*2 + 1] = Q;
    }
}

// ============================================================
// combo: finalize BN1 (blocks 0-63) + embed prep (64-191) +
//        conv2 weight collapse (192-203). All independent.
// ============================================================
__global__ void __launch_bounds__(256) combo_k(const float* __restrict__ gamma,
                                               const float* __restrict__ beta,
                                               const float* __restrict__ embed,
                                               const float* __restrict__ w2)
{
    int bb = blockIdx.x;
    int t = threadIdx.x;
    if (bb < 64) {
        int c = bb;
        float s = 0.f, q = 0.f;
        for (int i = t; i < 512; i += 256) {
            s += g_part1[(c*512 + i)*2];
            q += g_part1[(c*512 + i)*2 + 1];
        }
        __shared__ float ss[256], s2[256];
        ss[t] = s; s2[t] = q; __syncthreads();
        for (int o = 128; o > 0; o >>= 1) {
            if (t < o) { ss[t] += ss[t+o]; s2[t] += s2[t+o]; }
            __syncthreads();
        }
        if (t == 0) {
            float inv = 1.f / (float)BNCNT;
            float mean = ss[0] * inv;
            float var = s2[0] * inv - mean*mean;
            float scale = gamma[c] * rsqrtf(var + EPSBN);
            g_bn1[c*2]   = scale;
            g_bn1[c*2+1] = beta[c] - mean*scale;
        }
    } else if (bb < 192) {
        int code = (bb - 64)*8 + (t >> 5);
        int lane = t & 31;
        float a = embed[code*64 + lane];
        float b2v = embed[code*64 + 32 + lane];
        __nv_bfloat16 ah = __float2bfloat16(a);
        __nv_bfloat16 bh = __float2bfloat16(b2v);
        g_ehi[code*64 + lane] = ah;
        g_ehi[code*64 + 32 + lane] = bh;
        g_elo[code*64 + lane] = __float2bfloat16(a - __bfloat162float(ah));
        g_elo[code*64 + 32 + lane] = __float2bfloat16(b2v - __bfloat162float(bh));
        float s = a*a + b2v*b2v;
#pragma unroll
        for (int o = 16; o > 0; o >>= 1)
            s += __shfl_down_sync(0xffffffffu, s, o);
        if (lane == 0) g_e2[code] = s;
    } else {
        int e = (bb - 192)*256 + t;
        if (e < 48*64) {
            int d = e & 63;
            int rest = e >> 6;
            int tap = rest & 3;
            int tx_ = tap & 1, ty_ = tap >> 1;
            int co = (rest >> 2) % 3;
            int ph = rest / 12;
            int px = ph & 1, py = ph >> 1;
            float s = 0.f;
            for (int ky = 0; ky < 3; ky++) {
                int mapy = (py == 0) ? ((ky == 0) ? 0 : 1) : ((ky < 2) ? 0 : 1);
                if (mapy != ty_) continue;
                for (int kx = 0; kx < 3; kx++) {
                    int mapx = (px == 0) ? ((kx == 0) ? 0 : 1) : ((kx < 2) ? 0 : 1);
                    if (mapx != tx_) continue;
                    s += w2[((co*64 + d)*3 + ky)*3 + kx];
                }
            }
            g_cw[e] = s;
        }
    }
}

// ============================================================
// VQ: fused BN+ReLU+bf16-split of A (from g_praw) + hi/lo 3-GEMM
// via mma.sync with cp.async double-buffered B (1 sync/chunk).
// Packed-key top-2 + exact fp32 refine. Writes indices only.
// ============================================================
#define VQ_AHI  0
#define VQ_ALO  8192
#define VQ_POOL 16384
#define VQ_B0H  33792
#define VQ_B0L  41984
#define VQ_B1H  50176
#define VQ_B1L  58368
#define VQ_E2   66560
#define VQ_SMEM_SZ 70656

__global__ void __launch_bounds__(256,2) vq_k(const float* __restrict__ embed,
                                              float* __restrict__ out)
{
    extern __shared__ __align__(16) char vsmem[];
    __shared__ float s_ss[128];
    int t = threadIdx.x;
    int w = t >> 5, lane = t & 31;
    int rt = w & 1;
    int cq = w >> 1;
    int row0 = blockIdx.x * 64;
    unsigned int uBase = (unsigned int)__cvta_generic_to_shared(vsmem);
    const char* ehp = (const char*)g_ehi;
    const char* elp = (const char*)g_elo;

    if (t < 128) s_ss[t] = g_bn1[t];

    {
        unsigned int bh = uBase + VQ_B0H;
        unsigned int bl = uBase + VQ_B0L;
#pragma unroll
        for (int j = 0; j < 4; j++) {
            int idx = t + j*256;
            int e = idx & 511;
            int r = e >> 3, kc = e & 7;
            unsigned int doff = (unsigned int)((r*8 + (kc ^ (r & 7))) << 4);
            if (idx < 512) CP_ASYNC16(bh + doff, ehp + e*16);
            else           CP_ASYNC16(bl + doff, elp + e*16);
        }
        CP_COMMIT();
    }
    ((float4*)(vsmem + VQ_E2))[t] = ((const float4*)g_e2)[t];
    __syncthreads();

    {
        float* pool = (float*)(vsmem + VQ_POOL);
        uint4* ah4 = (uint4*)(vsmem + VQ_AHI);
        uint4* al4 = (uint4*)(vsmem + VQ_ALO);
#pragma unroll
        for (int j = 0; j < 2; j++) {
            int e8 = t + j*256;
            int r = e8 >> 3, c8 = e8 & 7;
            int k0 = c8*8;
            const float4* pr = (const float4*)(g_praw + (size_t)(row0 + r)*64 + k0);
            float4 v0 = pr[0], v1 = pr[1];
            float vv[8] = {v0.x, v0.y, v0.z, v0.w, v1.x, v1.y, v1.z, v1.w};
            unsigned hh[8], ll[8];
#pragma unroll
            for (int i = 0; i < 8; i++) {
                float vb = fmaxf(fmaf(vv[i], s_ss[(k0+i)*2], s_ss[(k0+i)*2+1]), 0.f);
                vv[i] = vb;
                __nv_bfloat16 hb = __float2bfloat16(vb);
                hh[i] = __bfloat16_as_ushort(hb);
                ll[i] = __bfloat16_as_ushort(__float2bfloat16(vb - __bfloat162float(hb)));
            }
            float* pp = pool + r*68 + k0;
            ((float4*)pp)[0] = make_float4(vv[0], vv[1], vv[2], vv[3]);
            ((float4*)pp)[1] = make_float4(vv[4], vv[5], vv[6], vv[7]);
            int dst = r*8 + (c8 ^ (r & 7));
            uint4 H, L;
            H.x = (hh[1]<<16)|hh[0]; H.y = (hh[3]<<16)|hh[2];
            H.z = (hh[5]<<16)|hh[4]; H.w = (hh[7]<<16)|hh[6];
            L.x = (ll[1]<<16)|ll[0]; L.y = (ll[3]<<16)|ll[2];
            L.z = (ll[5]<<16)|ll[4]; L.w = (ll[7]<<16)|ll[6];
            ah4[dst] = H;
            al4[dst] = L;
        }
    }
    CP_WAIT0();
    __syncthreads();

    unsigned int afrag[2][2][4][4];
    {
        unsigned int aHiB = uBase + VQ_AHI;
        unsigned int aLoB = uBase + VQ_ALO;
        int ahalf = lane >> 4;
#pragma unroll
        for (int rt2 = 0; rt2 < 2; rt2++) {
            int ar = rt*32 + rt2*16 + (lane & 15);
#pragma unroll
            for (int ks = 0; ks < 4; ks++) {
                unsigned int off = (unsigned int)(ar*128 + (((ks*2 + ahalf) ^ (ar & 7)) << 4));
                LDSM_X4(afrag[0][rt2][ks][0], afrag[0][rt2][ks][1], afrag[0][rt2][ks][2], afrag[0][rt2][ks][3], aHiB + off);
                LDSM_X4(afrag[1][rt2][ks][0], afrag[1][rt2][ks][1], afrag[1][rt2][ks][2], afrag[1][rt2][ks][3], aLoB + off);
            }
        }
    }

    const float* sE2 = (const float*)(vsmem + VQ_E2);
    const float INF = __int_as_float(0x7f800000);
    float kk1[2][2], kk2[2][2];
#pragma unroll
    for (int i = 0; i < 2; i++)
#pragma unroll
        for (int j = 0; j < 2; j++) { kk1[i][j] = INF; kk2[i][j] = INF; }

    int brow = cq*16 + (lane >> 4)*8 + (lane & 7);
    int bkhalf = (lane >> 3) & 1;

    for (int ch = 0; ch < 16; ch++) {
        int cur = ch & 1;
        if (ch + 1 < 16) {
            unsigned int bh = uBase + (cur ? VQ_B0H : VQ_B1H);
            unsigned int bl = uBase + (cur ? VQ_B0L : VQ_B1L);
            const char* sh = ehp + (ch+1)*8192;
            const char* sl = elp + (ch+1)*8192;
#pragma unroll
            for (int j = 0; j < 4; j++) {
                int idx = t + j*256;
                int e = idx & 511;
                int r = e >> 3, kc = e & 7;
                unsigned int doff = (unsigned int)((r*8 + (kc ^ (r & 7))) << 4);
                if (idx < 512) CP_ASYNC16(bh + doff, sh + e*16);
                else           CP_ASYNC16(bl + doff, sl + e*16);
            }
            CP_COMMIT();
        }

        unsigned int eHiB = uBase + (cur ? VQ_B1H : VQ_B0H);
        unsigned int eLoB = uBase + (cur ? VQ_B1L : VQ_B0L);

        float acc[2][2][4];
#pragma unroll
        for (int i = 0; i < 2; i++)
#pragma unroll
            for (int j = 0; j < 2; j++)
#pragma unroll
                for (int q = 0; q < 4; q++) acc[i][j][q] = 0.f;

#pragma unroll
        for (int ks = 0; ks < 4; ks++) {
            int kc = ks*2 + bkhalf;
            unsigned int off = (unsigned int)(brow*128 + ((kc ^ (brow & 7)) << 4));
            unsigned int bh0, bh1, bh2, bh3, bl0, bl1, bl2, bl3;
            LDSM_X4(bh0, bh1, bh2, bh3, eHiB + off);
            LDSM_X4(bl0, bl1, bl2, bl3, eLoB + off);
            MMA16816(acc[0][0], afrag[0][0][ks][0], afrag[0][0][ks][1], afrag[0][0][ks][2], afrag[0][0][ks][3], bh0, bh1);
            MMA16816(acc[0][1], afrag[0][0][ks][0], afrag[0][0][ks][1], afrag[0][0][ks][2], afrag[0][0][ks][3], bh2, bh3);
            MMA16816(acc[1][0], afrag[0][1][ks][0], afrag[0][1][ks][1], afrag[0][1][ks][2], afrag[0][1][ks][3], bh0, bh1);
            MMA16816(acc[1][1], afrag[0][1][ks][0], afrag[0][1][ks][1], afrag[0][1][ks][2], afrag[0][1][ks][3], bh2, bh3);
            MMA16816(acc[0][0], afrag[0][0][ks][0], afrag[0][0][ks][1], afrag[0][0][ks][2], afrag[0][0][ks][3], bl0, bl1);
            MMA16816(acc[0][1], afrag[0][0][ks][0], afrag[0][0][ks][1], afrag[0][0][ks][2], afrag[0][0][ks][3], bl2, bl3);
            MMA16816(acc[1][0], afrag[0][1][ks][0], afrag[0][1][ks][1], afrag[0][1][ks][2], afrag[0][1][ks][3], bl0, bl1);
            MMA16816(acc[1][1], afrag[0][1][ks][0], afrag[0][1][ks][1], afrag[0][1][ks][2], afrag[0][1][ks][3], bl2, bl3);
            MMA16816(acc[0][0], afrag[1][0][ks][0], afrag[1][0][ks][1], afrag[1][0][ks][2], afrag[1][0][ks][3], bh0, bh1);
            MMA16816(acc[0][1], afrag[1][0][ks][0], afrag[1][0][ks][1], afrag[1][0][ks][2], afrag[1][0][ks][3], bh2, bh3);
            MMA16816(acc[1][0], afrag[1][1][ks][0], afrag[1][1][ks][1], afrag[1][1][ks][2], afrag[1][1][ks][3], bh0, bh1);
            MMA16816(acc[1][1], afrag[1][1][ks][0], afrag[1][1][ks][1], afrag[1][1][ks][2], afrag[1][1][ks][3], bh2, bh3);
        }

        int cb = ch*64 + cq*16 + (lane & 3)*2;
#pragma unroll
        for (int rt2 = 0; rt2 < 2; rt2++) {
#pragma unroll
            for (int ct = 0; ct < 2; ct++) {
                int c0 = cb + ct*8, c1 = c0 + 1;
                float e20 = sE2[c0], e21 = sE2[c1];
                float dA0 = fmaf(-2.f, acc[rt2][ct][0], e20);
                float dA1 = fmaf(-2.f, acc[rt2][ct][1], e21);
                float dB0 = fmaf(-2.f, acc[rt2][ct][2], e20);
                float dB1 = fmaf(-2.f, acc[rt2][ct][3], e21);
                float kA0 = __uint_as_float((__float_as_uint(dA0) & 0xFFFFFC00u) | (unsigned)c0);
                float kA1 = __uint_as_float((__float_as_uint(dA1) & 0xFFFFFC00u) | (unsigned)c1);
                float kB0 = __uint_as_float((__float_as_uint(dB0) & 0xFFFFFC00u) | (unsigned)c0);
                float kB1 = __uint_as_float((__float_as_uint(dB1) & 0xFFFFFC00u) | (unsigned)c1);
                float hi;
                hi = fmaxf(kk1[rt2][0], kA0); kk1[rt2][0] = fminf(kk1[rt2][0], kA0); kk2[rt2][0] = fminf(kk2[rt2][0], hi);
                hi = fmaxf(kk1[rt2][0], kA1); kk1[rt2][0] = fminf(kk1[rt2][0], kA1); kk2[rt2][0] = fminf(kk2[rt2][0], hi);
                hi = fmaxf(kk1[rt2][1], kB0); kk1[rt2][1] = fminf(kk1[rt2][1], kB0); kk2[rt2][1] = fminf(kk2[rt2][1], hi);
                hi = fmaxf(kk1[rt2][1], kB1); kk1[rt2][1] = fminf(kk1[rt2][1], kB1); kk2[rt2][1] = fminf(kk2[rt2][1], hi);
            }
        }

        if (ch + 1 < 16) CP_WAIT0();
        __syncthreads();
    }

    const unsigned FULL = 0xffffffffu;
#pragma unroll
    for (int off = 2; off > 0; off >>= 1) {
#pragma unroll
        for (int rt2 = 0; rt2 < 2; rt2++)
#pragma unroll
            for (int s = 0; s < 2; s++) {
                float o1 = __shfl_down_sync(FULL, kk1[rt2][s], off, 4);
                float o2 = __shfl_down_sync(FULL, kk2[rt2][s], off, 4);
                float hi = fmaxf(kk1[rt2][s], o1);
                kk1[rt2][s] = fminf(kk1[rt2][s], o1);
                kk2[rt2][s] = fminf(fminf(kk2[rt2][s], o2), hi);
            }
    }

    float* k1buf = (float*)(vsmem + VQ_B0H);
    float* k2buf = (float*)(vsmem + VQ_B0H + 1024);
    int* s_b1 = (int*)(vsmem + VQ_B0H + 2048);
    if ((lane & 3) == 0) {
        int g = lane >> 2;
#pragma unroll
        for (int rt2 = 0; rt2 < 2; rt2++) {
            int rA = rt*32 + rt2*16 + g;
            k1buf[rA*4 + cq]     = kk1[rt2][0];
            k2buf[rA*4 + cq]     = kk2[rt2][0];
            k1buf[(rA+8)*4 + cq] = kk1[rt2][1];
            k2buf[(rA+8)*4 + cq] = kk2[rt2][1];
        }
    }
    __syncthreads();

    const float* pool = (const float*)(vsmem + VQ_POOL);
    if (t < 64) {
        float m1 = INF;
#pragma unroll
        for (int q = 0; q < 4; q++) m1 = fminf(m1, k1buf[t*4 + q]);
        float m2 = INF;
#pragma unroll
        for (int q = 0; q < 4; q++) {
            float v1 = k1buf[t*4 + q], v2 = k2buf[t*4 + q];
            m2 = fminf(m2, (v1 > m1) ? v1 : INF);
            m2 = fminf(m2, (v2 > m1) ? v2 : INF);
        }
        int i1 = (int)(__float_as_uint(m1) & 1023u);
        int i2 = (int)(__float_as_uint(m2) & 1023u);
        int best = i1;
        if (i2 != i1) {
            const float4* frow = (const float4*)(pool + t*68);
            const float4* ea = (const float4*)(embed + (size_t)i1*64);
            const float4* eb = (const float4*)(embed + (size_t)i2*64);
            float da = 0.f, db = 0.f;
#pragma unroll
            for (int k = 0; k < 16; k++) {
                float4 f = frow[k], va = ea[k], vb = eb[k];
                da = fmaf(f.x, va.x, da); da = fmaf(f.y, va.y, da);
                da = fmaf(f.z, va.z, da); da = fmaf(f.w, va.w, da);
                db = fmaf(f.x, vb.x, db); db = fmaf(f.y, vb.y, db);
                db = fmaf(f.z, vb.z, db); db = fmaf(f.w, vb.w, db);
            }
            float dda = fmaf(-2.f, da, sE2[i1]);
            float ddb = fmaf(-2.f, db, sE2[i2]);
            if (better(ddb, i2, dda, i1)) best = i2;
        }
        s_b1[t] = best;
        g_idx[row0 + t] = best;
        out[YELEMS + row0 + t] = (float)best;
    }
    __syncthreads();

    float lacc = 0.f;
#pragma unroll
    for (int it = 0; it < 16; it++) {
        int e = it*256 + t;
        int r = e >> 6, d = e & 63;
        int ci = s_b1[r];
        float qv = embed[ci*64 + d];
        float fv = pool[r*68 + d];
        float df = qv - fv;
        lacc = fmaf(df, df, lacc);
    }

    float* s_red = (float*)(vsmem + VQ_B1H);
    s_red[t] = lacc;
    __syncthreads();
    for (int o = 128; o > 0; o >>= 1) {
        if (t < o) s_red[t] += s_red[t+o];
        __syncthreads();
    }
    if (t == 0) g_losspart[blockIdx.x] = s_red[0];
}

// ============================================================
// decoder: nearest-x2 upsample fused with conv2 (collapsed 2x2),
// quant gathered from embed via g_idx. Reg-capped for occ 2.
// ============================================================
#define DCK 16
__global__ void __launch_bounds__(256,2) conv2up_k(const float* __restrict__ embed,
                                                   const float* __restrict__ bias)
{
    __shared__ float s_q[DCK][18][34];
    __shared__ float s_cw[48][DCK];
    __shared__ int s_ci[612];
    int t = threadIdx.x;
    int tx = t & 15, ty = t >> 4;
    int x0 = blockIdx.x*32, y0 = blockIdx.y*16, bb = blockIdx.z;

    for (int e = t; e < 612; e += 256) {
        int r = e / 34, c = e % 34;
        int qy = y0 - 1 + r, qx = x0 - 1 + c;
        int ci = -1;
        if (qy >= 0 && qy < 128 && qx >= 0 && qx < 128)
            ci = g_idx[(bb*128 + qy)*128 + qx];
        s_ci[e] = ci;
    }

    float acc[2][2][2][3];
#pragma unroll
    for (int a1 = 0; a1 < 2; a1++)
#pragma unroll
        for (int a2 = 0; a2 < 2; a2++)
#pragma unroll
            for (int a3 = 0; a3 < 2; a3++)
#pragma unroll
                for (int a4 = 0; a4 < 3; a4++) acc[a1][a2][a3][a4] = 0.f;

    for (int ch = 0; ch < 64/DCK; ch++) {
        __syncthreads();
        for (int e = t; e < 48*DCK; e += 256) {
            int row = e >> 4, dl = e & (DCK-1);
            s_cw[row][dl] = g_cw[row*64 + ch*DCK + dl];
        }
        for (int e = t; e < 612*DCK; e += 256) {
            int dl = e & (DCK-1);
            int cell = e >> 4;
            int ci = s_ci[cell];
            float v = (ci >= 0) ? embed[ci*64 + ch*DCK + dl] : 0.f;
            s_q[dl][cell / 34][cell % 34] = v;
        }
        __syncthreads();

#pragma unroll 2
        for (int dl = 0; dl < DCK; dl++) {
            float qv[3][4];
#pragma unroll
            for (int a = 0; a < 3; a++)
#pragma unroll
                for (int c = 0; c < 4; c++)
                    qv[a][c] = s_q[dl][ty + a][2*tx + c];
#pragma unroll
            for (int co = 0; co < 3; co++)
#pragma unroll
                for (int py = 0; py < 2; py++)
#pragma unroll
                    for (int px = 0; px < 2; px++) {
#pragma unroll
                        for (int ty_ = 0; ty_ < 2; ty_++)
#pragma unroll
                            for (int tx_ = 0; tx_ < 2; tx_++) {
                                float wv = s_cw[((py*2+px)*3+co)*4 + ty_*2+tx_][dl];
#pragma unroll
                                for (int xi = 0; xi < 2; xi++)
                                    acc[xi][py][px][co] =
                                        fmaf(qv[py+ty_][xi+px+tx_], wv, acc[xi][py][px][co]);
                            }
                    }
        }
    }

    int qy = y0 + ty;
#pragma unroll
    for (int co = 0; co < 3; co++) {
        float bv = bias[co];
#pragma unroll
        for (int xi = 0; xi < 2; xi++) {
            int qx = x0 + 2*tx + xi;
#pragma unroll
            for (int py = 0; py < 2; py++)
#pragma unroll
                for (int px = 0; px < 2; px++) {
                    int Y = 2*qy + py, X = 2*qx + px;
                    g_y2[((bb*3 + co) << 16) + (Y << 8) + X] = acc[xi][py][px][co] + bv;
                }
        }
    }
}

// ============================================================
// BN2 stats (float4)
// ============================================================
__global__ void __launch_bounds__(256) stats3_k()
{
    int c = blockIdx.x, s = blockIdx.y, t = threadIdx.x;
    const float4* src = (const float4*)g_y2;
    float sum = 0.f, sq = 0.f;
    int i0 = s * 4096;
    for (int i = i0 + t; i < i0 + 4096; i += 256) {
        int b = i >> 14, p4 = i & 16383;
        float4 v = src[((b*3 + c) << 14) + p4];
        sum += v.x + v.y + v.z + v.w;
        sq = fmaf(v.x, v.x, sq); sq = fmaf(v.y, v.y, sq);
        sq = fmaf(v.z, v.z, sq); sq = fmaf(v.w, v.w, sq);
    }
    __shared__ float ss[256], s2[256];
    ss[t] = sum; s2[t] = sq; __syncthreads();
    for (int o = 128; o > 0; o >>= 1) {
        if (t < o) { ss[t] += ss[t+o]; s2[t] += s2[t+o]; }
        __syncthreads();
    }
    if (t == 0) { g_part2[(c*32 + s)*2] = ss[0]; g_part2[(c*32 + s)*2 + 1] = s2[0]; }
}

// finalize BN2 + loss output (2048 loss partials)
__global__ void __launch_bounds__(256) fin2loss_k(const float* __restrict__ gamma,
                                                  const float* __restrict__ beta,
                                                  float* __restrict__ out)
{
    int t = threadIdx.x;
    if (t < 3) {
        float sum = 0.f, sq = 0.f;
        for (int s = 0; s < 32; s++) { sum += g_part2[(t*32+s)*2]; sq += g_part2[(t*32+s)*2+1]; }
        float inv = 1.f / (float)BNCNT;
        float mean = sum * inv;
        float var = sq * inv - mean*mean;
        float scale = gamma[t] * rsqrtf(var + EPSBN);
        g_bn2[t*2]   = scale;
        g_bn2[t*2+1] = beta[t] - mean*scale;
    }
    __shared__ float s[256];
    float acc = 0.f;
#pragma unroll
    for (int j = 0; j < 8; j++) acc += g_losspart[t + j*256];
    s[t] = acc;
    __syncthreads();
    for (int o = 128; o > 0; o >>= 1) {
        if (t < o) s[t] += s[t+o];
        __syncthreads();
    }
    if (t == 0) out[YELEMS + NPTS] = 0.25f * s[0] / (float)(NPTS * DD);
}

// ============================================================
// BN2 apply + tanh -> d_out (float4)
// ============================================================
__global__ void __launch_bounds__(256) bn2tanh_k(float* __restrict__ out)
{
    int e4 = blockIdx.x*256 + threadIdx.x;
    int c = (e4 >> 14) % 3;
    float sc = g_bn2[c*2], sh = g_bn2[c*2+1];
    float4 v = ((const float4*)g_y2)[e4];
    float4 r;
    r.x = tanhf(fmaf(v.x, sc, sh));
    r.y = tanhf(fmaf(v.y, sc, sh));
    r.z = tanhf(fmaf(v.z, sc, sh));
    r.w = tanhf(fmaf(v.w, sc, sh));
    ((float4*)out)[e4] = r;
}

// ============================================================
extern "C" void kernel_launch(void* const* d_in, const int* in_sizes, int n_in,
                              void* d_out, int out_size)
{
    const float* x   = (const float*)d_in[0];
    const float* w1  = (const float*)d_in[1];
    const float* b1  = (const float*)d_in[2];
    const float* g1  = (const float*)d_in[3];
    const float* be1 = (const float*)d_in[4];
    const float* em  = (const float*)d_in[5];
    const float* w2  = (const float*)d_in[6];
    const float* b2  = (const float*)d_in[7];
    const float* g2  = (const float*)d_in[8];
    const float* be2 = (const float*)d_in[9];
    float* out = (float*)d_out;
    (void)in_sizes; (void)n_in; (void)out_size;

    cudaFuncSetAttribute(conv1pool_k, cudaFuncAttributeMaxDynamicSharedMemorySize, C1_SMEM);
    cudaFuncSetAttribute(vq_k, cudaFuncAttributeMaxDynamicSharedMemorySize, VQ_SMEM_SZ);

    conv1pool_k<<<dim3(8,8,8), dim3(32,8), C1_SMEM>>>(x, w1, b1);   // 0
    combo_k<<<204, 256>>>(g1, be1, em, w2);                         // 1
    vq_k<<<NPTS/64, 256, VQ_SMEM_SZ>>>(em, out);                    // 2
    conv2up_k<<<dim3(4,8,8), 256>>>(em, b2);                        // 3
    stats3_k<<<dim3(3,32), 256>>>();                                // 4
    fin2loss_k<<<1, 256>>>(g2, be2, out);                           // 5
    bn2tanh_k<<<YELEMS/1024, 256>>>(out);                           // 6
}